// round 2
// baseline (speedup 1.0000x reference)
#include <cuda_runtime.h>
#include <math.h>

#define T_ 16
#define B_ 8
#define H_ 224
#define W_ 224
#define C_ 3
#define CH_ 32
#define OUT_ 10
#define WF_ 113           // W/2 + 1
#define TB_ (T_*B_)

// ---------------- device scratch (static: no runtime allocation) ----------------
__device__ float2 g_tw[W_];                          // e^{+i 2pi k/224} table (use conj)
__device__ float2 g_R[(size_t)TB_*H_*WF_];           // row rFFT results
__device__ float  g_mag[(size_t)TB_*H_*WF_];         // log1p|spec|
__device__ float  g_magup[(size_t)TB_*H_*W_];        // resized to W=224
__device__ float  g_epart[TB_*WF_];                  // per-(tb,wf) energy partial sums
__device__ int    g_count[T_*B_*CH_];                // spike counts per (t,b,ch)

// ---------------- init: twiddles + zero ALL counters (4096) every call ----------------
__global__ void init_kernel() {
    int i = blockIdx.x * blockDim.x + threadIdx.x;
    if (i < W_) {
        double a = (2.0 * 3.141592653589793238462643 * (double)i) / 224.0;
        g_tw[i] = make_float2((float)cos(a), (float)sin(a));
    }
    if (i < T_ * B_ * CH_) g_count[i] = 0;
}

// ---------------- row rFFT: gray = mean(RGB), 224 real -> 113 complex ----------------
// grid (H_, TB_), block 128
__global__ void __launch_bounds__(128) rowfft_kernel(const float* __restrict__ x) {
    int h  = blockIdx.x;
    int tb = blockIdx.y;
    __shared__ float  gsh[W_];
    __shared__ float2 tw[W_];
    int tid = threadIdx.x;
    for (int i = tid; i < W_; i += 128) tw[i] = g_tw[i];
    const float* row = x + (((size_t)tb * H_ + h) * W_) * 3;
    for (int w = tid; w < W_; w += 128) {
        float r = row[w*3+0], g = row[w*3+1], b = row[w*3+2];
        gsh[w] = (r + g + b) * (1.0f / 3.0f);
    }
    __syncthreads();
    int wf = tid;
    if (wf < WF_) {
        float re = 0.f, im = 0.f;
        int idx = 0;
        #pragma unroll 4
        for (int w = 0; w < W_; ++w) {
            float2 t = tw[idx];
            float gv = gsh[w];
            re += gv * t.x;
            im -= gv * t.y;
            idx += wf; if (idx >= W_) idx -= W_;
        }
        g_R[((size_t)tb * H_ + h) * WF_ + wf] = make_float2(re, im);
    }
}

// ---------------- column FFT (complex 224-pt) + mag + energy partial ----------------
// grid (WF_, TB_), block 224 (7 full warps)
__global__ void __launch_bounds__(224) colfft_kernel() {
    int wf = blockIdx.x;
    int tb = blockIdx.y;
    __shared__ float2 col[H_];
    __shared__ float2 tw[H_];
    __shared__ float  red[7];
    int tid = threadIdx.x;   // 0..223
    tw[tid]  = g_tw[tid];
    col[tid] = g_R[((size_t)tb * H_ + tid) * WF_ + wf];
    __syncthreads();

    int hf = tid;
    float re = 0.f, im = 0.f;
    int idx = 0;
    #pragma unroll 4
    for (int h = 0; h < H_; ++h) {
        float2 t = tw[idx];
        float2 v = col[h];
        re += v.x * t.x + v.y * t.y;   // (vx+ivy)*(c - is)
        im += v.y * t.x - v.x * t.y;
        idx += hf; if (idx >= H_) idx -= H_;
    }
    float m = log1pf(sqrtf(re * re + im * im));
    g_mag[((size_t)tb * H_ + hf) * WF_ + wf] = m;

    // deterministic block-sum for spectral energy
    float s = m;
    #pragma unroll
    for (int o = 16; o; o >>= 1) s += __shfl_down_sync(0xffffffffu, s, o);
    if ((tid & 31) == 0) red[tid >> 5] = s;
    __syncthreads();
    if (tid == 0) {
        float tot = 0.f;
        #pragma unroll
        for (int i = 0; i < 7; ++i) tot += red[i];
        g_epart[tb * WF_ + wf] = tot;
    }
}

// ---------------- linear resize along W: 113 -> 224 (jax half-pixel, edge clamp) ----------------
__global__ void resize_kernel() {
    int i = blockIdx.x * blockDim.x + threadIdx.x;
    const int N = TB_ * H_ * W_;
    if (i >= N) return;
    int w  = i % W_;
    int h  = (i / W_) % H_;
    int tb = i / (W_ * H_);
    float u  = (w + 0.5f) * ((float)WF_ / (float)W_) - 0.5f;
    float fj = floorf(u);
    float f  = u - fj;
    int j  = (int)fj;
    int i0 = j;     if (i0 < 0) i0 = 0; if (i0 > WF_-1) i0 = WF_-1;
    int i1 = j + 1; if (i1 < 0) i1 = 0; if (i1 > WF_-1) i1 = WF_-1;
    const float* mrow = g_mag + ((size_t)tb * H_ + h) * WF_;
    g_magup[i] = (1.0f - f) * mrow[i0] + f * mrow[i1];
}

// ---------------- fused conv3x3(4->32) + LIF over all T, V in registers ----------------
// grid (14,14,B_), block (16,16)
__global__ void __launch_bounds__(256) convlif_kernel(const float* __restrict__ x,
                                                      const float* __restrict__ cw,
                                                      const float* __restrict__ cb) {
    __shared__ float  wsh[9 * 4 * CH_];   // [p][ic][ch], matches HWIO flatten
    __shared__ float  bsh[CH_];
    __shared__ float4 tile[18][18];       // 16x16 + halo, 4 input channels packed
    __shared__ int    cnt[T_ * CH_];

    int tx = threadIdx.x, ty = threadIdx.y;
    int tid = ty * 16 + tx;
    int lane = tid & 31;
    int b = blockIdx.z;
    int by0 = blockIdx.y * 16, bx0 = blockIdx.x * 16;

    for (int i = tid; i < 9 * 4 * CH_; i += 256) wsh[i] = cw[i];
    if (tid < CH_) bsh[tid] = cb[tid];
    for (int i = tid; i < T_ * CH_; i += 256) cnt[i] = 0;

    float V[CH_];
    #pragma unroll
    for (int ch = 0; ch < CH_; ++ch) V[ch] = 0.f;

    for (int t = 0; t < T_; ++t) {
        __syncthreads();   // protect tile from previous iteration / weight load
        // load 18x18 tile: RGB from x_seq, 4th channel from mag_up; zero pad (SAME)
        for (int i = tid; i < 18 * 18; i += 256) {
            int ly = i / 18, lx = i % 18;
            int gy = by0 + ly - 1, gx = bx0 + lx - 1;
            float4 v = make_float4(0.f, 0.f, 0.f, 0.f);
            if (gy >= 0 && gy < H_ && gx >= 0 && gx < W_) {
                size_t base = (((size_t)t * B_ + b) * H_ + gy) * W_ + gx;
                const float* px = x + base * 3;
                v.x = px[0]; v.y = px[1]; v.z = px[2];
                v.w = g_magup[base];
            }
            tile[ly][lx] = v;
        }
        __syncthreads();

        float acc[CH_];
        #pragma unroll
        for (int ch = 0; ch < CH_; ++ch) acc[ch] = bsh[ch];

        #pragma unroll 1
        for (int p = 0; p < 9; ++p) {
            int ky = p / 3, kx = p - ky * 3;
            float4 v = tile[ty + ky][tx + kx];
            const float4* wp = (const float4*)&wsh[p * 4 * CH_];
            #pragma unroll
            for (int ic = 0; ic < 4; ++ic) {
                float vi = (ic == 0) ? v.x : (ic == 1) ? v.y : (ic == 2) ? v.z : v.w;
                #pragma unroll
                for (int c4 = 0; c4 < 8; ++c4) {
                    float4 w4 = wp[ic * 8 + c4];
                    acc[c4*4+0] += vi * w4.x;
                    acc[c4*4+1] += vi * w4.y;
                    acc[c4*4+2] += vi * w4.z;
                    acc[c4*4+3] += vi * w4.w;
                }
            }
        }

        // LIF update + spike + soft reset
        unsigned smask = 0u;
        #pragma unroll
        for (int ch = 0; ch < CH_; ++ch) {
            V[ch] = 0.9f * V[ch] + acc[ch];
            if (V[ch] - 1.0f > 0.0f) { V[ch] -= 1.0f; smask |= (1u << ch); }
        }

        // per-warp per-channel counts via ballot; lane L owns channel L
        int myc = 0;
        #pragma unroll
        for (int ch = 0; ch < CH_; ++ch) {
            unsigned bal = __ballot_sync(0xffffffffu, (smask >> ch) & 1u);
            if (lane == ch) myc = (int)__popc(bal);
        }
        atomicAdd(&cnt[t * CH_ + lane], myc);
    }

    __syncthreads();
    for (int i = tid; i < T_ * CH_; i += 256) {
        int t = i >> 5, ch = i & 31;
        atomicAdd(&g_count[(t * B_ + b) * CH_ + ch], cnt[i]);
    }
}

// ---------------- finalize: logits, readout, spike rate, energy ----------------
__global__ void __launch_bounds__(256) finalize_kernel(const float* __restrict__ hw_g,
                                                       const float* __restrict__ hb_g,
                                                       float* __restrict__ out, int out_size) {
    __shared__ float hw[CH_ * OUT_];
    __shared__ float hb[OUT_];
    __shared__ float logits[T_ * B_ * OUT_];
    __shared__ float red[256];
    int tid = threadIdx.x;
    for (int i = tid; i < CH_ * OUT_; i += 256) hw[i] = hw_g[i];
    if (tid < OUT_) hb[tid] = hb_g[tid];
    __syncthreads();

    const float inv = 1.0f / ((float)(H_ * W_));
    for (int i = tid; i < T_ * B_ * OUT_; i += 256) {
        int o = i % OUT_;
        int tb = i / OUT_;
        float a = hb[o];
        const int* c = &g_count[tb * CH_];
        #pragma unroll
        for (int ch = 0; ch < CH_; ++ch)
            a += ((float)c[ch] * inv) * hw[ch * OUT_ + o];
        logits[i] = a;
    }
    __syncthreads();

    if (out_size >= B_*OUT_ + T_*B_*OUT_ + 2) {
        for (int i = tid; i < T_ * B_ * OUT_; i += 256)
            out[B_ * OUT_ + i] = logits[i];
    }
    if (tid < B_ * OUT_) {
        float s = 0.f;
        for (int t = 0; t < T_; ++t) s += logits[t * B_ * OUT_ + tid];
        out[tid] = s * (1.0f / (float)T_);
    }

    // spike rate: total spikes / (T*B*H*W*CH), deterministic reduce
    {
        float s = 0.f;
        for (int i = tid; i < T_ * B_ * CH_; i += 256) s += (float)g_count[i];
        red[tid] = s;
        __syncthreads();
        for (int st = 128; st; st >>= 1) { if (tid < st) red[tid] += red[tid + st]; __syncthreads(); }
        if (tid == 0 && out_size >= B_*OUT_ + T_*B_*OUT_ + 1)
            out[B_*OUT_ + T_*B_*OUT_] = red[0] / ((float)T_ * B_ * CH_ * H_ * W_);
        __syncthreads();
    }
    // energy: mean over all (t,b,h,wf) of mag, deterministic reduce
    {
        float s = 0.f;
        for (int i = tid; i < TB_ * WF_; i += 256) s += g_epart[i];
        red[tid] = s;
        __syncthreads();
        for (int st = 128; st; st >>= 1) { if (tid < st) red[tid] += red[tid + st]; __syncthreads(); }
        if (tid == 0 && out_size >= B_*OUT_ + T_*B_*OUT_ + 2)
            out[B_*OUT_ + T_*B_*OUT_ + 1] = red[0] / ((float)T_ * B_ * H_ * WF_);
    }
}

// ---------------- launch ----------------
extern "C" void kernel_launch(void* const* d_in, const int* in_sizes, int n_in,
                              void* d_out, int out_size) {
    const float* x_seq  = (const float*)d_in[0];   // (T,B,H,W,C)
    const float* conv_w = (const float*)d_in[1];   // (3,3,4,32) HWIO
    const float* conv_b = (const float*)d_in[2];   // (32,)
    const float* head_w = (const float*)d_in[3];   // (32,10)
    const float* head_b = (const float*)d_in[4];   // (10,)
    float* out = (float*)d_out;

    // FIX R1: must cover T*B*CH = 4096 counter slots every call (was 512 ->
    // counters >=512 accumulated across graph replays -> post-timing divergence)
    init_kernel<<<16, 256>>>();

    rowfft_kernel<<<dim3(H_, TB_), 128>>>(x_seq);

    colfft_kernel<<<dim3(WF_, TB_), 224>>>();

    {
        int n = TB_ * H_ * W_;
        resize_kernel<<<(n + 255) / 256, 256>>>();
    }

    convlif_kernel<<<dim3(W_/16, H_/16, B_), dim3(16, 16)>>>(x_seq, conv_w, conv_b);

    finalize_kernel<<<1, 256>>>(head_w, head_b, out, out_size);
}

// round 3
// speedup vs baseline: 1.6440x; 1.6440x over previous
#include <cuda_runtime.h>
#include <math.h>

#define T_ 16
#define B_ 8
#define H_ 224
#define W_ 224
#define C_ 3
#define CH_ 32
#define OUT_ 10
#define WF_ 113           // W/2 + 1
#define WFP_ 120          // padded to multiple of 8 for vectorized colfft
#define NWG_ 15           // WFP_/8 wf-groups
#define TB_ (T_*B_)

// ---------------- device scratch (static: no runtime allocation) ----------------
__device__ float2 g_tw[W_];                          // e^{+i 2pi k/224} table
__device__ float2 g_R[(size_t)TB_*H_*WFP_];          // row rFFT results (padded)
__device__ float  g_mag[(size_t)TB_*H_*WF_];         // log1p|spec|
__device__ float  g_epart[TB_*NWG_];                 // energy partial sums
__device__ int    g_count[T_*B_*CH_];                // spike counts per (t,b,ch)

// ---------------- init: twiddles + zero ALL counters every call ----------------
__global__ void init_kernel() {
    int i = blockIdx.x * blockDim.x + threadIdx.x;
    if (i < W_) {
        double a = (2.0 * 3.141592653589793238462643 * (double)i) / 224.0;
        g_tw[i] = make_float2((float)cos(a), (float)sin(a));
    }
    if (i < T_ * B_ * CH_) g_count[i] = 0;
}

// ---------------- row rFFT: 8 rows per block, rotation-recurrence twiddles ----------------
// grid (TB_*H_/8), block 128. Thread owns wf (0..119; >=113 are pad), 8 rows.
__global__ void __launch_bounds__(128) rowfft_kernel(const float* __restrict__ x) {
    __shared__ float  gsh[8][W_];     // 8 gray rows
    __shared__ float2 twsh[W_];
    int tid = threadIdx.x;
    int rid0 = blockIdx.x * 8;        // first row (tb*H + h), rows contiguous in x

    for (int i = tid; i < W_; i += 128) twsh[i] = g_tw[i];
    // stage gray = mean(RGB) for 8 contiguous rows
    const float* xb = x + (size_t)rid0 * W_ * 3;
    for (int i = tid; i < 8 * W_; i += 128) {
        float r = xb[i*3+0], g = xb[i*3+1], b = xb[i*3+2];
        ((float*)gsh)[i] = (r + g + b) * (1.0f / 3.0f);
    }
    __syncthreads();

    int wf = tid;
    if (wf >= WFP_) return;

    float re[8], im[8];
    #pragma unroll
    for (int r = 0; r < 8; ++r) { re[r] = 0.f; im[r] = 0.f; }

    const float cs = twsh[wf].x, ss = -twsh[wf].y;  // step e^{-i 2pi wf/224}
    float c, s;
    for (int wb = 0; wb < W_; wb += 16) {
        int idx = (wb * wf) % W_;                   // exact resync
        c = twsh[idx].x; s = -twsh[idx].y;
        #pragma unroll
        for (int w0 = 0; w0 < 16; w0 += 4) {
            float4 g[8];
            #pragma unroll
            for (int r = 0; r < 8; ++r)
                g[r] = *(const float4*)&gsh[r][wb + w0];
            #pragma unroll
            for (int k = 0; k < 4; ++k) {
                #pragma unroll
                for (int r = 0; r < 8; ++r) {
                    float gv = (k==0)?g[r].x:(k==1)?g[r].y:(k==2)?g[r].z:g[r].w;
                    re[r] += gv * c;
                    im[r] += gv * s;
                }
                float cn = c * cs - s * ss;
                s = c * ss + s * cs;
                c = cn;
            }
        }
    }
    #pragma unroll
    for (int r = 0; r < 8; ++r)
        g_R[(size_t)(rid0 + r) * WFP_ + wf] = make_float2(re[r], im[r]);
}

// ---------------- column FFT: 8 wf-columns per block, rotation recurrence ----------------
// grid (NWG_, TB_), block 224. Thread owns hf, accumulates 8 wf outputs.
__global__ void __launch_bounds__(224) colfft_kernel() {
    __shared__ float2 csh[8][H_];     // 8 wf-columns, indexed [j][h]
    __shared__ float2 twsh[H_];
    __shared__ float  red[7];
    int tid = threadIdx.x;            // 0..223
    int wf0 = blockIdx.x * 8;
    int tb  = blockIdx.y;

    twsh[tid] = g_tw[tid];
    {   // stage: thread tid loads 8 consecutive wf for h=tid (4x float4, coalesced 64B)
        const float4* src = (const float4*)(g_R + ((size_t)tb * H_ + tid) * WFP_ + wf0);
        #pragma unroll
        for (int q = 0; q < 4; ++q) {
            float4 v = src[q];
            csh[q*2+0][tid] = make_float2(v.x, v.y);
            csh[q*2+1][tid] = make_float2(v.z, v.w);
        }
    }
    __syncthreads();

    int hf = tid;
    float rr[8], ri[8];
    #pragma unroll
    for (int j = 0; j < 8; ++j) { rr[j] = 0.f; ri[j] = 0.f; }

    const float cs = twsh[hf].x, ss = -twsh[hf].y;
    for (int hb = 0; hb < H_; hb += 16) {
        int idx = (hb * hf) % H_;
        float c = twsh[idx].x, s = -twsh[idx].y;
        #pragma unroll
        for (int h0 = 0; h0 < 16; h0 += 2) {
            float4 v[8];
            #pragma unroll
            for (int j = 0; j < 8; ++j)
                v[j] = *(const float4*)&csh[j][hb + h0];
            #pragma unroll
            for (int j = 0; j < 8; ++j) {
                rr[j] += v[j].x * c - v[j].y * s;
                ri[j] += v[j].x * s + v[j].y * c;
            }
            { float cn = c*cs - s*ss; s = c*ss + s*cs; c = cn; }
            #pragma unroll
            for (int j = 0; j < 8; ++j) {
                rr[j] += v[j].z * c - v[j].w * s;
                ri[j] += v[j].z * s + v[j].w * c;
            }
            { float cn = c*cs - s*ss; s = c*ss + s*cs; c = cn; }
        }
    }

    // mag + log1p + energy (only real wf < 113)
    float esum = 0.f;
    float* mrow = g_mag + ((size_t)tb * H_ + hf) * WF_;
    #pragma unroll
    for (int j = 0; j < 8; ++j) {
        int wf = wf0 + j;
        if (wf < WF_) {
            float m = log1pf(sqrtf(rr[j]*rr[j] + ri[j]*ri[j]));
            mrow[wf] = m;
            esum += m;
        }
    }
    // deterministic block reduce (224 threads = 7 warps)
    #pragma unroll
    for (int o = 16; o; o >>= 1) esum += __shfl_down_sync(0xffffffffu, esum, o);
    if ((tid & 31) == 0) red[tid >> 5] = esum;
    __syncthreads();
    if (tid == 0) {
        float tot = 0.f;
        #pragma unroll
        for (int i = 0; i < 7; ++i) tot += red[i];
        g_epart[tb * NWG_ + blockIdx.x] = tot;
    }
}

// ---------------- fused conv3x3(4->32) + LIF over all T, V in registers ----------------
// 4th channel interpolated inline from g_mag (resize fused). grid (14,14,B_), block (16,16)
__global__ void __launch_bounds__(256) convlif_kernel(const float* __restrict__ x,
                                                      const float* __restrict__ cw,
                                                      const float* __restrict__ cb) {
    __shared__ float  wsh[9 * 4 * CH_];
    __shared__ float  bsh[CH_];
    __shared__ float4 tile[18][18];
    __shared__ int    cnt[T_ * CH_];

    int tx = threadIdx.x, ty = threadIdx.y;
    int tid = ty * 16 + tx;
    int lane = tid & 31;
    int b = blockIdx.z;
    int by0 = blockIdx.y * 16, bx0 = blockIdx.x * 16;

    for (int i = tid; i < 9 * 4 * CH_; i += 256) wsh[i] = cw[i];
    if (tid < CH_) bsh[tid] = cb[tid];
    for (int i = tid; i < T_ * CH_; i += 256) cnt[i] = 0;

    float V[CH_];
    #pragma unroll
    for (int ch = 0; ch < CH_; ++ch) V[ch] = 0.f;

    const float sc = (float)WF_ / (float)W_;
    for (int t = 0; t < T_; ++t) {
        __syncthreads();
        for (int i = tid; i < 18 * 18; i += 256) {
            int ly = i / 18, lx = i % 18;
            int gy = by0 + ly - 1, gx = bx0 + lx - 1;
            float4 v = make_float4(0.f, 0.f, 0.f, 0.f);
            if (gy >= 0 && gy < H_ && gx >= 0 && gx < W_) {
                size_t base = (((size_t)t * B_ + b) * H_ + gy) * W_ + gx;
                const float* px = x + base * 3;
                v.x = px[0]; v.y = px[1]; v.z = px[2];
                // inline W-resize 113 -> 224 (half-pixel, edge clamp)
                float u  = (gx + 0.5f) * sc - 0.5f;
                float fj = floorf(u);
                float f  = u - fj;
                int j = (int)fj;
                int i0 = j < 0 ? 0 : (j > WF_-1 ? WF_-1 : j);
                int i1 = j+1 < 0 ? 0 : (j+1 > WF_-1 ? WF_-1 : j+1);
                const float* mrow = g_mag + (((size_t)t * B_ + b) * H_ + gy) * WF_;
                v.w = (1.0f - f) * mrow[i0] + f * mrow[i1];
            }
            tile[ly][lx] = v;
        }
        __syncthreads();

        float acc[CH_];
        #pragma unroll
        for (int ch = 0; ch < CH_; ++ch) acc[ch] = bsh[ch];

        #pragma unroll 1
        for (int p = 0; p < 9; ++p) {
            int ky = p / 3, kx = p - ky * 3;
            float4 v = tile[ty + ky][tx + kx];
            const float4* wp = (const float4*)&wsh[p * 4 * CH_];
            #pragma unroll
            for (int ic = 0; ic < 4; ++ic) {
                float vi = (ic == 0) ? v.x : (ic == 1) ? v.y : (ic == 2) ? v.z : v.w;
                #pragma unroll
                for (int c4 = 0; c4 < 8; ++c4) {
                    float4 w4 = wp[ic * 8 + c4];
                    acc[c4*4+0] += vi * w4.x;
                    acc[c4*4+1] += vi * w4.y;
                    acc[c4*4+2] += vi * w4.z;
                    acc[c4*4+3] += vi * w4.w;
                }
            }
        }

        unsigned smask = 0u;
        #pragma unroll
        for (int ch = 0; ch < CH_; ++ch) {
            V[ch] = 0.9f * V[ch] + acc[ch];
            if (V[ch] - 1.0f > 0.0f) { V[ch] -= 1.0f; smask |= (1u << ch); }
        }

        int myc = 0;
        #pragma unroll
        for (int ch = 0; ch < CH_; ++ch) {
            unsigned bal = __ballot_sync(0xffffffffu, (smask >> ch) & 1u);
            if (lane == ch) myc = (int)__popc(bal);
        }
        atomicAdd(&cnt[t * CH_ + lane], myc);
    }

    __syncthreads();
    for (int i = tid; i < T_ * CH_; i += 256) {
        int t = i >> 5, ch = i & 31;
        atomicAdd(&g_count[(t * B_ + b) * CH_ + ch], cnt[i]);
    }
}

// ---------------- finalize: logits, readout, spike rate, energy ----------------
__global__ void __launch_bounds__(256) finalize_kernel(const float* __restrict__ hw_g,
                                                       const float* __restrict__ hb_g,
                                                       float* __restrict__ out, int out_size) {
    __shared__ float hw[CH_ * OUT_];
    __shared__ float hb[OUT_];
    __shared__ float logits[T_ * B_ * OUT_];
    __shared__ float red[256];
    int tid = threadIdx.x;
    for (int i = tid; i < CH_ * OUT_; i += 256) hw[i] = hw_g[i];
    if (tid < OUT_) hb[tid] = hb_g[tid];
    __syncthreads();

    const float inv = 1.0f / ((float)(H_ * W_));
    for (int i = tid; i < T_ * B_ * OUT_; i += 256) {
        int o = i % OUT_;
        int tb = i / OUT_;
        float a = hb[o];
        const int* c = &g_count[tb * CH_];
        #pragma unroll
        for (int ch = 0; ch < CH_; ++ch)
            a += ((float)c[ch] * inv) * hw[ch * OUT_ + o];
        logits[i] = a;
    }
    __syncthreads();

    if (out_size >= B_*OUT_ + T_*B_*OUT_ + 2) {
        for (int i = tid; i < T_ * B_ * OUT_; i += 256)
            out[B_ * OUT_ + i] = logits[i];
    }
    if (tid < B_ * OUT_) {
        float s = 0.f;
        for (int t = 0; t < T_; ++t) s += logits[t * B_ * OUT_ + tid];
        out[tid] = s * (1.0f / (float)T_);
    }

    {   // spike rate
        float s = 0.f;
        for (int i = tid; i < T_ * B_ * CH_; i += 256) s += (float)g_count[i];
        red[tid] = s;
        __syncthreads();
        for (int st = 128; st; st >>= 1) { if (tid < st) red[tid] += red[tid + st]; __syncthreads(); }
        if (tid == 0 && out_size >= B_*OUT_ + T_*B_*OUT_ + 1)
            out[B_*OUT_ + T_*B_*OUT_] = red[0] / ((float)T_ * B_ * CH_ * H_ * W_);
        __syncthreads();
    }
    {   // spectral energy
        float s = 0.f;
        for (int i = tid; i < TB_ * NWG_; i += 256) s += g_epart[i];
        red[tid] = s;
        __syncthreads();
        for (int st = 128; st; st >>= 1) { if (tid < st) red[tid] += red[tid + st]; __syncthreads(); }
        if (tid == 0 && out_size >= B_*OUT_ + T_*B_*OUT_ + 2)
            out[B_*OUT_ + T_*B_*OUT_ + 1] = red[0] / ((float)T_ * B_ * H_ * WF_);
    }
}

// ---------------- launch ----------------
extern "C" void kernel_launch(void* const* d_in, const int* in_sizes, int n_in,
                              void* d_out, int out_size) {
    const float* x_seq  = (const float*)d_in[0];
    const float* conv_w = (const float*)d_in[1];
    const float* conv_b = (const float*)d_in[2];
    const float* head_w = (const float*)d_in[3];
    const float* head_b = (const float*)d_in[4];
    float* out = (float*)d_out;

    init_kernel<<<16, 256>>>();
    rowfft_kernel<<<TB_ * H_ / 8, 128>>>(x_seq);
    colfft_kernel<<<dim3(NWG_, TB_), 224>>>();
    convlif_kernel<<<dim3(W_/16, H_/16, B_), dim3(16, 16)>>>(x_seq, conv_w, conv_b);
    finalize_kernel<<<1, 256>>>(head_w, head_b, out, out_size);
}

// round 5
// speedup vs baseline: 2.2621x; 1.3760x over previous
#include <cuda_runtime.h>
#include <math.h>

#define T_ 16
#define B_ 8
#define H_ 224
#define W_ 224
#define C_ 3
#define CH_ 32
#define OUT_ 10
#define WF_ 113           // W/2 + 1
#define WFP_ 120          // padded to multiple of 8 for vectorized colfft
#define NWG_ 15           // WFP_/8 wf-groups
#define TB_ (T_*B_)

typedef unsigned long long ull;

#define FMA_F32X2(d, a, b) asm("fma.rn.f32x2 %0, %1, %2, %0;" : "+l"(d) : "l"(a), "l"(b))
#define PACK_F32X2(d, lo, hi) asm("mov.b64 %0, {%1, %2};" : "=l"(d) : "f"(lo), "f"(hi))
#define UNPACK_F32X2(lo, hi, d) asm("mov.b64 {%0, %1}, %2;" : "=f"(lo), "=f"(hi) : "l"(d))

// ---------------- device scratch (static: no runtime allocation) ----------------
__device__ float2 g_tw[W_];                          // e^{+i 2pi k/224} table
__device__ float2 g_R[(size_t)TB_*H_*WFP_];          // row rFFT results (padded)
__device__ float  g_mag[(size_t)TB_*H_*WF_];         // log1p|spec|
__device__ float  g_epart[TB_*NWG_];                 // energy partial sums
__device__ int    g_count[T_*B_*CH_];                // spike counts per (t,b,ch)

// ---------------- init: twiddles + zero ALL counters every call ----------------
__global__ void init_kernel() {
    int i = blockIdx.x * blockDim.x + threadIdx.x;
    if (i < W_) {
        double a = (2.0 * 3.141592653589793238462643 * (double)i) / 224.0;
        g_tw[i] = make_float2((float)cos(a), (float)sin(a));
    }
    if (i < T_ * B_ * CH_) g_count[i] = 0;
}

// ---------------- row rFFT: 8 rows per block, rotation-recurrence twiddles ----------------
__global__ void __launch_bounds__(128) rowfft_kernel(const float* __restrict__ x) {
    __shared__ float  gsh[8][W_];
    __shared__ float2 twsh[W_];
    int tid = threadIdx.x;
    int rid0 = blockIdx.x * 8;

    for (int i = tid; i < W_; i += 128) twsh[i] = g_tw[i];
    const float* xb = x + (size_t)rid0 * W_ * 3;
    for (int i = tid; i < 8 * W_; i += 128) {
        float r = xb[i*3+0], g = xb[i*3+1], b = xb[i*3+2];
        ((float*)gsh)[i] = (r + g + b) * (1.0f / 3.0f);
    }
    __syncthreads();

    int wf = tid;
    if (wf >= WFP_) return;

    float re[8], im[8];
    #pragma unroll
    for (int r = 0; r < 8; ++r) { re[r] = 0.f; im[r] = 0.f; }

    const float cs = twsh[wf].x, ss = -twsh[wf].y;
    float c, s;
    for (int wb = 0; wb < W_; wb += 16) {
        int idx = (wb * wf) % W_;
        c = twsh[idx].x; s = -twsh[idx].y;
        #pragma unroll
        for (int w0 = 0; w0 < 16; w0 += 4) {
            float4 g[8];
            #pragma unroll
            for (int r = 0; r < 8; ++r)
                g[r] = *(const float4*)&gsh[r][wb + w0];
            #pragma unroll
            for (int k = 0; k < 4; ++k) {
                #pragma unroll
                for (int r = 0; r < 8; ++r) {
                    float gv = (k==0)?g[r].x:(k==1)?g[r].y:(k==2)?g[r].z:g[r].w;
                    re[r] += gv * c;
                    im[r] += gv * s;
                }
                float cn = c * cs - s * ss;
                s = c * ss + s * cs;
                c = cn;
            }
        }
    }
    #pragma unroll
    for (int r = 0; r < 8; ++r)
        g_R[(size_t)(rid0 + r) * WFP_ + wf] = make_float2(re[r], im[r]);
}

// ---------------- column FFT: 8 wf-columns per block, rotation recurrence ----------------
__global__ void __launch_bounds__(224) colfft_kernel() {
    __shared__ float2 csh[8][H_];
    __shared__ float2 twsh[H_];
    __shared__ float  red[7];
    int tid = threadIdx.x;
    int wf0 = blockIdx.x * 8;
    int tb  = blockIdx.y;

    twsh[tid] = g_tw[tid];
    {
        const float4* src = (const float4*)(g_R + ((size_t)tb * H_ + tid) * WFP_ + wf0);
        #pragma unroll
        for (int q = 0; q < 4; ++q) {
            float4 v = src[q];
            csh[q*2+0][tid] = make_float2(v.x, v.y);
            csh[q*2+1][tid] = make_float2(v.z, v.w);
        }
    }
    __syncthreads();

    int hf = tid;
    float rr[8], ri[8];
    #pragma unroll
    for (int j = 0; j < 8; ++j) { rr[j] = 0.f; ri[j] = 0.f; }

    const float cs = twsh[hf].x, ss = -twsh[hf].y;
    for (int hb = 0; hb < H_; hb += 16) {
        int idx = (hb * hf) % H_;
        float c = twsh[idx].x, s = -twsh[idx].y;
        #pragma unroll
        for (int h0 = 0; h0 < 16; h0 += 2) {
            float4 v[8];
            #pragma unroll
            for (int j = 0; j < 8; ++j)
                v[j] = *(const float4*)&csh[j][hb + h0];
            #pragma unroll
            for (int j = 0; j < 8; ++j) {
                rr[j] += v[j].x * c - v[j].y * s;
                ri[j] += v[j].x * s + v[j].y * c;
            }
            { float cn = c*cs - s*ss; s = c*ss + s*cs; c = cn; }
            #pragma unroll
            for (int j = 0; j < 8; ++j) {
                rr[j] += v[j].z * c - v[j].w * s;
                ri[j] += v[j].z * s + v[j].w * c;
            }
            { float cn = c*cs - s*ss; s = c*ss + s*cs; c = cn; }
        }
    }

    float esum = 0.f;
    float* mrow = g_mag + ((size_t)tb * H_ + hf) * WF_;
    #pragma unroll
    for (int j = 0; j < 8; ++j) {
        int wf = wf0 + j;
        if (wf < WF_) {
            float m = log1pf(sqrtf(rr[j]*rr[j] + ri[j]*ri[j]));
            mrow[wf] = m;
            esum += m;
        }
    }
    #pragma unroll
    for (int o = 16; o; o >>= 1) esum += __shfl_down_sync(0xffffffffu, esum, o);
    if ((tid & 31) == 0) red[tid >> 5] = esum;
    __syncthreads();
    if (tid == 0) {
        float tot = 0.f;
        #pragma unroll
        for (int i = 0; i < 7; ++i) tot += red[i];
        g_epart[tb * NWG_ + blockIdx.x] = tot;
    }
}

// ---------------- fused conv3x3(4->32) + LIF, f32x2 pixel-pair packed ----------------
// Block 256 thr = 8 warps. Warp w owns channels 4w..4w+3 over all 256 px of a 16x16 tile.
// Lane l: row r = l>>1, x-half hx = l&1 (8-px strip). Thread: 8 px x 4 ch, acc as f32x2
// over pixel pairs. SoA channel planes (18 rows x 20 stride), double buffered.
#define PLS_ 360   // 18*20 floats per plane

__device__ __forceinline__ void fill_tile(float* __restrict__ pls,
                                          const float* __restrict__ x,
                                          int t, int b, int by0, int bx0, int tid) {
    const float sc = (float)WF_ / (float)W_;
    for (int i = tid; i < 18 * 18; i += 256) {
        int ly = i / 18, lx = i % 18;
        int gy = by0 + ly - 1, gx = bx0 + lx - 1;
        float vr = 0.f, vg = 0.f, vb = 0.f, vm = 0.f;
        if (gy >= 0 && gy < H_ && gx >= 0 && gx < W_) {
            size_t base = (((size_t)t * B_ + b) * H_ + gy) * W_ + gx;
            const float* px = x + base * 3;
            vr = px[0]; vg = px[1]; vb = px[2];
            float u  = (gx + 0.5f) * sc - 0.5f;
            float fj = floorf(u);
            float f  = u - fj;
            int j = (int)fj;
            int i0 = j < 0 ? 0 : (j > WF_-1 ? WF_-1 : j);
            int i1 = j+1 < 0 ? 0 : (j+1 > WF_-1 ? WF_-1 : j+1);
            const float* mrow = g_mag + (((size_t)t * B_ + b) * H_ + gy) * WF_;
            vm = (1.0f - f) * mrow[i0] + f * mrow[i1];
        }
        int o = ly * 20 + lx;
        pls[0*PLS_ + o] = vr;
        pls[1*PLS_ + o] = vg;
        pls[2*PLS_ + o] = vb;
        pls[3*PLS_ + o] = vm;
    }
}

__global__ void __launch_bounds__(256, 2) convlif_kernel(const float* __restrict__ x,
                                                         const float* __restrict__ cw,
                                                         const float* __restrict__ cb) {
    __shared__ ulonglong2 wsh2[9][4][16];          // duplicated {w,w} pairs: [p][ic][ch/2]
    __shared__ float bsh[CH_];
    __shared__ __align__(16) float planes[2][4 * PLS_];
    __shared__ int cnt[T_][CH_];

    int tid = threadIdx.x;
    int w = tid >> 5;          // warp = channel group (4 channels 4w..4w+3)
    int l = tid & 31;
    int r = l >> 1;            // output row within tile
    int hx = l & 1;            // x half
    int c0 = hx * 8;           // first output col within tile
    int b = blockIdx.z;
    int by0 = blockIdx.y * 16, bx0 = blockIdx.x * 16;

    // duplicated packed weights
    for (int i = tid; i < 9 * 4 * CH_; i += 256) {
        int p = i >> 7, rest = i & 127;
        int ic = rest >> 5, ch = rest & 31;
        float wv = cw[i];
        float* dst = (float*)&wsh2[p][ic][0];
        dst[2*ch + 0] = wv;
        dst[2*ch + 1] = wv;
    }
    if (tid < CH_) bsh[tid] = cb[tid];
    for (int i = tid; i < T_ * CH_; i += 256) ((int*)cnt)[i] = 0;
    __syncthreads();

    ull bias2[4];
    #pragma unroll
    for (int c = 0; c < 4; ++c) { float bc = bsh[4*w + c]; PACK_F32X2(bias2[c], bc, bc); }

    float V[4][8];
    #pragma unroll
    for (int c = 0; c < 4; ++c)
        #pragma unroll
        for (int j = 0; j < 8; ++j) V[c][j] = 0.f;

    fill_tile(&planes[0][0], x, 0, b, by0, bx0, tid);
    __syncthreads();

    #pragma unroll 1
    for (int t = 0; t < T_; ++t) {
        int bb = t & 1;
        // prefetch next timestep's tile into the other buffer (overlaps compute)
        if (t + 1 < T_) fill_tile(&planes[bb ^ 1][0], x, t + 1, b, by0, bx0, tid);

        ull acc[4][4];
        #pragma unroll
        for (int c = 0; c < 4; ++c)
            #pragma unroll
            for (int pr = 0; pr < 4; ++pr) acc[c][pr] = bias2[c];

        #pragma unroll
        for (int ky = 0; ky < 3; ++ky) {
            #pragma unroll
            for (int ic = 0; ic < 4; ++ic) {
                const float* pl = &planes[bb][ic * PLS_ + (r + ky) * 20 + c0];
                float4 a0 = *(const float4*)(pl + 0);
                float4 a1 = *(const float4*)(pl + 4);
                float4 a2 = *(const float4*)(pl + 8);
                float v[12] = {a0.x,a0.y,a0.z,a0.w, a1.x,a1.y,a1.z,a1.w, a2.x,a2.y,a2.z,a2.w};
                ull P[9];
                #pragma unroll
                for (int i = 0; i < 9; ++i) PACK_F32X2(P[i], v[i], v[i+1]);
                #pragma unroll
                for (int kx = 0; kx < 3; ++kx) {
                    int p = ky * 3 + kx;
                    ulonglong2 q0 = wsh2[p][ic][2*w + 0];
                    ulonglong2 q1 = wsh2[p][ic][2*w + 1];
                    #pragma unroll
                    for (int pr = 0; pr < 4; ++pr) {
                        ull a = P[2*pr + kx];
                        FMA_F32X2(acc[0][pr], a, q0.x);
                        FMA_F32X2(acc[1][pr], a, q0.y);
                        FMA_F32X2(acc[2][pr], a, q1.x);
                        FMA_F32X2(acc[3][pr], a, q1.y);
                    }
                }
            }
        }

        // LIF + per-channel spike counts
        int n[4] = {0, 0, 0, 0};
        #pragma unroll
        for (int c = 0; c < 4; ++c) {
            #pragma unroll
            for (int pr = 0; pr < 4; ++pr) {
                float lo, hi;
                UNPACK_F32X2(lo, hi, acc[c][pr]);
                float v0 = fmaf(0.9f, V[c][2*pr+0], lo);
                float v1 = fmaf(0.9f, V[c][2*pr+1], hi);
                if (v0 > 1.0f) { v0 -= 1.0f; n[c]++; }
                if (v1 > 1.0f) { v1 -= 1.0f; n[c]++; }
                V[c][2*pr+0] = v0;
                V[c][2*pr+1] = v1;
            }
        }
        int p01 = n[0] | (n[1] << 16);
        int p23 = n[2] | (n[3] << 16);
        #pragma unroll
        for (int o = 16; o; o >>= 1) {
            p01 += __shfl_down_sync(0xffffffffu, p01, o);
            p23 += __shfl_down_sync(0xffffffffu, p23, o);
        }
        if (l == 0) {   // lane 0 of warp w is the exclusive writer for channels 4w..4w+3
            cnt[t][4*w + 0] += p01 & 0xffff;
            cnt[t][4*w + 1] += p01 >> 16;
            cnt[t][4*w + 2] += p23 & 0xffff;
            cnt[t][4*w + 3] += p23 >> 16;
        }
        __syncthreads();   // next buffer filled + current buffer free for t+2 fill
    }

    for (int i = tid; i < T_ * CH_; i += 256) {
        int t = i >> 5, ch = i & 31;
        atomicAdd(&g_count[(t * B_ + b) * CH_ + ch], cnt[t][ch]);
    }
}

// ---------------- finalize: logits, readout, spike rate, energy ----------------
__global__ void __launch_bounds__(256) finalize_kernel(const float* __restrict__ hw_g,
                                                       const float* __restrict__ hb_g,
                                                       float* __restrict__ out, int out_size) {
    __shared__ float hw[CH_ * OUT_];
    __shared__ float hb[OUT_];
    __shared__ float logits[T_ * B_ * OUT_];
    __shared__ float red[256];
    int tid = threadIdx.x;
    for (int i = tid; i < CH_ * OUT_; i += 256) hw[i] = hw_g[i];
    if (tid < OUT_) hb[tid] = hb_g[tid];
    __syncthreads();

    const float inv = 1.0f / ((float)(H_ * W_));
    for (int i = tid; i < T_ * B_ * OUT_; i += 256) {
        int o = i % OUT_;
        int tb = i / OUT_;
        float a = hb[o];
        const int* c = &g_count[tb * CH_];
        #pragma unroll
        for (int ch = 0; ch < CH_; ++ch)
            a += ((float)c[ch] * inv) * hw[ch * OUT_ + o];
        logits[i] = a;
    }
    __syncthreads();

    if (out_size >= B_*OUT_ + T_*B_*OUT_ + 2) {
        for (int i = tid; i < T_ * B_ * OUT_; i += 256)
            out[B_ * OUT_ + i] = logits[i];
    }
    if (tid < B_ * OUT_) {
        float s = 0.f;
        for (int t = 0; t < T_; ++t) s += logits[t * B_ * OUT_ + tid];
        out[tid] = s * (1.0f / (float)T_);
    }

    {   // spike rate
        float s = 0.f;
        for (int i = tid; i < T_ * B_ * CH_; i += 256) s += (float)g_count[i];
        red[tid] = s;
        __syncthreads();
        for (int st = 128; st; st >>= 1) { if (tid < st) red[tid] += red[tid + st]; __syncthreads(); }
        if (tid == 0 && out_size >= B_*OUT_ + T_*B_*OUT_ + 1)
            out[B_*OUT_ + T_*B_*OUT_] = red[0] / ((float)T_ * B_ * CH_ * H_ * W_);
        __syncthreads();
    }
    {   // spectral energy
        float s = 0.f;
        for (int i = tid; i < TB_ * NWG_; i += 256) s += g_epart[i];
        red[tid] = s;
        __syncthreads();
        for (int st = 128; st; st >>= 1) { if (tid < st) red[tid] += red[tid + st]; __syncthreads(); }
        if (tid == 0 && out_size >= B_*OUT_ + T_*B_*OUT_ + 2)
            out[B_*OUT_ + T_*B_*OUT_ + 1] = red[0] / ((float)T_ * B_ * H_ * WF_);
    }
}

// ---------------- launch ----------------
extern "C" void kernel_launch(void* const* d_in, const int* in_sizes, int n_in,
                              void* d_out, int out_size) {
    const float* x_seq  = (const float*)d_in[0];
    const float* conv_w = (const float*)d_in[1];
    const float* conv_b = (const float*)d_in[2];
    const float* head_w = (const float*)d_in[3];
    const float* head_b = (const float*)d_in[4];
    float* out = (float*)d_out;

    init_kernel<<<16, 256>>>();
    rowfft_kernel<<<TB_ * H_ / 8, 128>>>(x_seq);
    colfft_kernel<<<dim3(NWG_, TB_), 224>>>();
    convlif_kernel<<<dim3(W_/16, H_/16, B_), 256>>>(x_seq, conv_w, conv_b);
    finalize_kernel<<<1, 256>>>(head_w, head_b, out, out_size);
}

// round 6
// speedup vs baseline: 2.6396x; 1.1669x over previous
#include <cuda_runtime.h>
#include <math.h>

#define T_ 16
#define B_ 8
#define H_ 224
#define W_ 224
#define C_ 3
#define CH_ 32
#define OUT_ 10
#define WF_ 113           // W/2 + 1
#define WFP_ 120          // padded to multiple of 8 for vectorized colfft
#define NWG_ 15           // WFP_/8 wf-groups
#define TB_ (T_*B_)

typedef unsigned long long ull;

#define FMA_F32X2(d, a, b) asm("fma.rn.f32x2 %0, %1, %2, %0;" : "+l"(d) : "l"(a), "l"(b))
#define PACK_F32X2(d, lo, hi) asm("mov.b64 %0, {%1, %2};" : "=l"(d) : "f"(lo), "f"(hi))
#define UNPACK_F32X2(lo, hi, d) asm("mov.b64 {%0, %1}, %2;" : "=f"(lo), "=f"(hi) : "l"(d))

// ---------------- constant memory: conv weights/bias (warp-uniform -> uniform LDC path, no LDS) --
__constant__ __align__(16) float c_w[9 * 4 * CH_];   // [p][ic][ch], HWIO flatten; ch-pairs 8B-aligned
__constant__ __align__(16) float c_b[CH_];

// ---------------- device scratch (static: no runtime allocation) ----------------
__device__ float2 g_tw[W_];                          // e^{+i 2pi k/224} table
__device__ float2 g_R[(size_t)TB_*H_*WFP_];          // row rFFT results (padded)
__device__ float  g_mag[(size_t)TB_*H_*WF_];         // log1p|spec|
__device__ float  g_epart[TB_*NWG_];                 // energy partial sums
__device__ int    g_count[T_*B_*CH_];                // spike counts per (t,b,ch)

// ---------------- init: twiddles + zero ALL counters every call ----------------
__global__ void init_kernel() {
    int i = blockIdx.x * blockDim.x + threadIdx.x;
    if (i < W_) {
        double a = (2.0 * 3.141592653589793238462643 * (double)i) / 224.0;
        g_tw[i] = make_float2((float)cos(a), (float)sin(a));
    }
    if (i < T_ * B_ * CH_) g_count[i] = 0;
}

// ---------------- row rFFT: 8 rows per block, rotation-recurrence twiddles ----------------
__global__ void __launch_bounds__(128) rowfft_kernel(const float* __restrict__ x) {
    __shared__ float  gsh[8][W_];
    __shared__ float2 twsh[W_];
    int tid = threadIdx.x;
    int rid0 = blockIdx.x * 8;

    for (int i = tid; i < W_; i += 128) twsh[i] = g_tw[i];
    const float* xb = x + (size_t)rid0 * W_ * 3;
    for (int i = tid; i < 8 * W_; i += 128) {
        float r = xb[i*3+0], g = xb[i*3+1], b = xb[i*3+2];
        ((float*)gsh)[i] = (r + g + b) * (1.0f / 3.0f);
    }
    __syncthreads();

    int wf = tid;
    if (wf >= WFP_) return;

    float re[8], im[8];
    #pragma unroll
    for (int r = 0; r < 8; ++r) { re[r] = 0.f; im[r] = 0.f; }

    const float cs = twsh[wf].x, ss = -twsh[wf].y;
    float c, s;
    for (int wb = 0; wb < W_; wb += 16) {
        int idx = (wb * wf) % W_;
        c = twsh[idx].x; s = -twsh[idx].y;
        #pragma unroll
        for (int w0 = 0; w0 < 16; w0 += 4) {
            float4 g[8];
            #pragma unroll
            for (int r = 0; r < 8; ++r)
                g[r] = *(const float4*)&gsh[r][wb + w0];
            #pragma unroll
            for (int k = 0; k < 4; ++k) {
                #pragma unroll
                for (int r = 0; r < 8; ++r) {
                    float gv = (k==0)?g[r].x:(k==1)?g[r].y:(k==2)?g[r].z:g[r].w;
                    re[r] += gv * c;
                    im[r] += gv * s;
                }
                float cn = c * cs - s * ss;
                s = c * ss + s * cs;
                c = cn;
            }
        }
    }
    #pragma unroll
    for (int r = 0; r < 8; ++r)
        g_R[(size_t)(rid0 + r) * WFP_ + wf] = make_float2(re[r], im[r]);
}

// ---------------- column FFT: 8 wf-columns per block, rotation recurrence ----------------
__global__ void __launch_bounds__(224) colfft_kernel() {
    __shared__ float2 csh[8][H_];
    __shared__ float2 twsh[H_];
    __shared__ float  red[7];
    int tid = threadIdx.x;
    int wf0 = blockIdx.x * 8;
    int tb  = blockIdx.y;

    twsh[tid] = g_tw[tid];
    {
        const float4* src = (const float4*)(g_R + ((size_t)tb * H_ + tid) * WFP_ + wf0);
        #pragma unroll
        for (int q = 0; q < 4; ++q) {
            float4 v = src[q];
            csh[q*2+0][tid] = make_float2(v.x, v.y);
            csh[q*2+1][tid] = make_float2(v.z, v.w);
        }
    }
    __syncthreads();

    int hf = tid;
    float rr[8], ri[8];
    #pragma unroll
    for (int j = 0; j < 8; ++j) { rr[j] = 0.f; ri[j] = 0.f; }

    const float cs = twsh[hf].x, ss = -twsh[hf].y;
    for (int hb = 0; hb < H_; hb += 16) {
        int idx = (hb * hf) % H_;
        float c = twsh[idx].x, s = -twsh[idx].y;
        #pragma unroll
        for (int h0 = 0; h0 < 16; h0 += 2) {
            float4 v[8];
            #pragma unroll
            for (int j = 0; j < 8; ++j)
                v[j] = *(const float4*)&csh[j][hb + h0];
            #pragma unroll
            for (int j = 0; j < 8; ++j) {
                rr[j] += v[j].x * c - v[j].y * s;
                ri[j] += v[j].x * s + v[j].y * c;
            }
            { float cn = c*cs - s*ss; s = c*ss + s*cs; c = cn; }
            #pragma unroll
            for (int j = 0; j < 8; ++j) {
                rr[j] += v[j].z * c - v[j].w * s;
                ri[j] += v[j].z * s + v[j].w * c;
            }
            { float cn = c*cs - s*ss; s = c*ss + s*cs; c = cn; }
        }
    }

    float esum = 0.f;
    float* mrow = g_mag + ((size_t)tb * H_ + hf) * WF_;
    #pragma unroll
    for (int j = 0; j < 8; ++j) {
        int wf = wf0 + j;
        if (wf < WF_) {
            float m = log1pf(sqrtf(rr[j]*rr[j] + ri[j]*ri[j]));
            mrow[wf] = m;
            esum += m;
        }
    }
    #pragma unroll
    for (int o = 16; o; o >>= 1) esum += __shfl_down_sync(0xffffffffu, esum, o);
    if ((tid & 31) == 0) red[tid >> 5] = esum;
    __syncthreads();
    if (tid == 0) {
        float tot = 0.f;
        #pragma unroll
        for (int i = 0; i < 7; ++i) tot += red[i];
        g_epart[tb * NWG_ + blockIdx.x] = tot;
    }
}

// ---------------- fused conv3x3(4->32) + LIF, f32x2 CHANNEL-pair packed ----------------
// Warp w owns channels 4w..4w+3. Lane l: row r=l>>1, x-half hx=l&1 (8-px strip).
// acc[c2][px] = f32x2 over adjacent channels {4w+2c2, 4w+2c2+1}; weight pair = one aligned
// 8B constant load (warp-uniform -> uniform path, zero LDS). Activations broadcast-packed {a,a}.
#define PLS_ 360   // 18*20 floats per plane

__device__ __forceinline__ void fill_tile(float* __restrict__ pls,
                                          const float* __restrict__ x,
                                          int t, int b, int by0, int bx0, int tid) {
    const float sc = (float)WF_ / (float)W_;
    for (int i = tid; i < 18 * 18; i += 256) {
        int ly = i / 18, lx = i % 18;
        int gy = by0 + ly - 1, gx = bx0 + lx - 1;
        float vr = 0.f, vg = 0.f, vb = 0.f, vm = 0.f;
        if (gy >= 0 && gy < H_ && gx >= 0 && gx < W_) {
            size_t base = (((size_t)t * B_ + b) * H_ + gy) * W_ + gx;
            const float* px = x + base * 3;
            vr = px[0]; vg = px[1]; vb = px[2];
            float u  = (gx + 0.5f) * sc - 0.5f;
            float fj = floorf(u);
            float f  = u - fj;
            int j = (int)fj;
            int i0 = j < 0 ? 0 : (j > WF_-1 ? WF_-1 : j);
            int i1 = j+1 < 0 ? 0 : (j+1 > WF_-1 ? WF_-1 : j+1);
            const float* mrow = g_mag + (((size_t)t * B_ + b) * H_ + gy) * WF_;
            vm = (1.0f - f) * mrow[i0] + f * mrow[i1];
        }
        int o = ly * 20 + lx;
        pls[0*PLS_ + o] = vr;
        pls[1*PLS_ + o] = vg;
        pls[2*PLS_ + o] = vb;
        pls[3*PLS_ + o] = vm;
    }
}

__global__ void __launch_bounds__(256, 2) convlif_kernel(const float* __restrict__ x) {
    __shared__ __align__(16) float planes[2][4 * PLS_];
    __shared__ int cnt[T_][CH_];

    int tid = threadIdx.x;
    int w = tid >> 5;          // warp = channel group (4 channels 4w..4w+3)
    int l = tid & 31;
    int r = l >> 1;            // output row within tile
    int hx = l & 1;            // x half
    int c0 = hx * 8;           // first output col within tile
    int b = blockIdx.z;
    int by0 = blockIdx.y * 16, bx0 = blockIdx.x * 16;

    for (int i = tid; i < T_ * CH_; i += 256) ((int*)cnt)[i] = 0;

    const ull* cw2 = (const ull*)c_w;    // channel-pair view: [(p*4+ic)*16 + ch/2]
    const ull* cb2 = (const ull*)c_b;

    ull bias2[2];
    bias2[0] = cb2[2*w + 0];
    bias2[1] = cb2[2*w + 1];

    ull K09;
    { float k = 0.9f; PACK_F32X2(K09, k, k); }

    ull V2[2][8];
    #pragma unroll
    for (int c = 0; c < 2; ++c)
        #pragma unroll
        for (int j = 0; j < 8; ++j) V2[c][j] = 0ull;

    fill_tile(&planes[0][0], x, 0, b, by0, bx0, tid);
    __syncthreads();

    #pragma unroll 1
    for (int t = 0; t < T_; ++t) {
        int bb = t & 1;
        if (t + 1 < T_) fill_tile(&planes[bb ^ 1][0], x, t + 1, b, by0, bx0, tid);

        ull acc[2][8];
        #pragma unroll
        for (int c = 0; c < 2; ++c)
            #pragma unroll
            for (int j = 0; j < 8; ++j) acc[c][j] = bias2[c];

        #pragma unroll
        for (int ky = 0; ky < 3; ++ky) {
            #pragma unroll
            for (int ic = 0; ic < 4; ++ic) {
                const float* pl = &planes[bb][ic * PLS_ + (r + ky) * 20 + c0];
                float4 a0 = *(const float4*)(pl + 0);
                float4 a1 = *(const float4*)(pl + 4);
                float2 a2 = *(const float2*)(pl + 8);
                ull A[10];
                PACK_F32X2(A[0], a0.x, a0.x);
                PACK_F32X2(A[1], a0.y, a0.y);
                PACK_F32X2(A[2], a0.z, a0.z);
                PACK_F32X2(A[3], a0.w, a0.w);
                PACK_F32X2(A[4], a1.x, a1.x);
                PACK_F32X2(A[5], a1.y, a1.y);
                PACK_F32X2(A[6], a1.z, a1.z);
                PACK_F32X2(A[7], a1.w, a1.w);
                PACK_F32X2(A[8], a2.x, a2.x);
                PACK_F32X2(A[9], a2.y, a2.y);
                #pragma unroll
                for (int kx = 0; kx < 3; ++kx) {
                    int p = ky * 3 + kx;
                    ull w0 = cw2[(p * 4 + ic) * 16 + 2*w + 0];   // warp-uniform constant load
                    ull w1 = cw2[(p * 4 + ic) * 16 + 2*w + 1];
                    #pragma unroll
                    for (int j = 0; j < 8; ++j) {
                        FMA_F32X2(acc[0][j], A[j + kx], w0);
                        FMA_F32X2(acc[1][j], A[j + kx], w1);
                    }
                }
            }
        }

        // LIF: V_new = 0.9*V + cur (packed FMA2), spike, soft reset, count
        int n[4] = {0, 0, 0, 0};
        #pragma unroll
        for (int c = 0; c < 2; ++c) {
            #pragma unroll
            for (int j = 0; j < 8; ++j) {
                FMA_F32X2(acc[c][j], V2[c][j], K09);     // acc = cur + 0.9*V
                float lo, hi;
                UNPACK_F32X2(lo, hi, acc[c][j]);
                if (lo > 1.0f) { lo -= 1.0f; n[2*c+0]++; }
                if (hi > 1.0f) { hi -= 1.0f; n[2*c+1]++; }
                PACK_F32X2(V2[c][j], lo, hi);
            }
        }
        int p01 = n[0] | (n[1] << 16);
        int p23 = n[2] | (n[3] << 16);
        #pragma unroll
        for (int o = 16; o; o >>= 1) {
            p01 += __shfl_down_sync(0xffffffffu, p01, o);
            p23 += __shfl_down_sync(0xffffffffu, p23, o);
        }
        if (l == 0) {   // lane 0 of warp w: exclusive writer for channels 4w..4w+3
            cnt[t][4*w + 0] += p01 & 0xffff;
            cnt[t][4*w + 1] += p01 >> 16;
            cnt[t][4*w + 2] += p23 & 0xffff;
            cnt[t][4*w + 3] += p23 >> 16;
        }
        __syncthreads();
    }

    for (int i = tid; i < T_ * CH_; i += 256) {
        int t = i >> 5, ch = i & 31;
        atomicAdd(&g_count[(t * B_ + b) * CH_ + ch], cnt[t][ch]);
    }
}

// ---------------- finalize: logits, readout, spike rate, energy ----------------
__global__ void __launch_bounds__(256) finalize_kernel(const float* __restrict__ hw_g,
                                                       const float* __restrict__ hb_g,
                                                       float* __restrict__ out, int out_size) {
    __shared__ float hw[CH_ * OUT_];
    __shared__ float hb[OUT_];
    __shared__ float logits[T_ * B_ * OUT_];
    __shared__ float red[256];
    int tid = threadIdx.x;
    for (int i = tid; i < CH_ * OUT_; i += 256) hw[i] = hw_g[i];
    if (tid < OUT_) hb[tid] = hb_g[tid];
    __syncthreads();

    const float inv = 1.0f / ((float)(H_ * W_));
    for (int i = tid; i < T_ * B_ * OUT_; i += 256) {
        int o = i % OUT_;
        int tb = i / OUT_;
        float a = hb[o];
        const int* c = &g_count[tb * CH_];
        #pragma unroll
        for (int ch = 0; ch < CH_; ++ch)
            a += ((float)c[ch] * inv) * hw[ch * OUT_ + o];
        logits[i] = a;
    }
    __syncthreads();

    if (out_size >= B_*OUT_ + T_*B_*OUT_ + 2) {
        for (int i = tid; i < T_ * B_ * OUT_; i += 256)
            out[B_ * OUT_ + i] = logits[i];
    }
    if (tid < B_ * OUT_) {
        float s = 0.f;
        for (int t = 0; t < T_; ++t) s += logits[t * B_ * OUT_ + tid];
        out[tid] = s * (1.0f / (float)T_);
    }

    {   // spike rate
        float s = 0.f;
        for (int i = tid; i < T_ * B_ * CH_; i += 256) s += (float)g_count[i];
        red[tid] = s;
        __syncthreads();
        for (int st = 128; st; st >>= 1) { if (tid < st) red[tid] += red[tid + st]; __syncthreads(); }
        if (tid == 0 && out_size >= B_*OUT_ + T_*B_*OUT_ + 1)
            out[B_*OUT_ + T_*B_*OUT_] = red[0] / ((float)T_ * B_ * CH_ * H_ * W_);
        __syncthreads();
    }
    {   // spectral energy
        float s = 0.f;
        for (int i = tid; i < TB_ * NWG_; i += 256) s += g_epart[i];
        red[tid] = s;
        __syncthreads();
        for (int st = 128; st; st >>= 1) { if (tid < st) red[tid] += red[tid + st]; __syncthreads(); }
        if (tid == 0 && out_size >= B_*OUT_ + T_*B_*OUT_ + 2)
            out[B_*OUT_ + T_*B_*OUT_ + 1] = red[0] / ((float)T_ * B_ * H_ * WF_);
    }
}

// ---------------- launch ----------------
extern "C" void kernel_launch(void* const* d_in, const int* in_sizes, int n_in,
                              void* d_out, int out_size) {
    const float* x_seq  = (const float*)d_in[0];
    const float* conv_w = (const float*)d_in[1];
    const float* conv_b = (const float*)d_in[2];
    const float* head_w = (const float*)d_in[3];
    const float* head_b = (const float*)d_in[4];
    float* out = (float*)d_out;

    // device->device copies into constant memory (graph-capturable, no allocation)
    cudaMemcpyToSymbolAsync(c_w, conv_w, 9 * 4 * CH_ * sizeof(float), 0, cudaMemcpyDeviceToDevice, 0);
    cudaMemcpyToSymbolAsync(c_b, conv_b, CH_ * sizeof(float), 0, cudaMemcpyDeviceToDevice, 0);

    init_kernel<<<16, 256>>>();
    rowfft_kernel<<<TB_ * H_ / 8, 128>>>(x_seq);
    colfft_kernel<<<dim3(NWG_, TB_), 224>>>();
    convlif_kernel<<<dim3(W_/16, H_/16, B_), 256>>>(x_seq);
    finalize_kernel<<<1, 256>>>(head_w, head_b, out, out_size);
}

// round 7
// speedup vs baseline: 3.1469x; 1.1922x over previous
#include <cuda_runtime.h>
#include <math.h>

#define T_ 16
#define B_ 8
#define H_ 224
#define W_ 224
#define C_ 3
#define CH_ 32
#define OUT_ 10
#define WF_ 113           // W/2 + 1
#define WFP_ 120          // padded to multiple of 8 for vectorized colfft
#define NWG_ 15           // WFP_/8 wf-groups
#define TB_ (T_*B_)

typedef unsigned long long ull;

#define FMA_F32X2(d, a, b) asm("fma.rn.f32x2 %0, %1, %2, %0;" : "+l"(d) : "l"(a), "l"(b))
#define PACK_F32X2(d, lo, hi) asm("mov.b64 %0, {%1, %2};" : "=l"(d) : "f"(lo), "f"(hi))
#define UNPACK_F32X2(lo, hi, d) asm("mov.b64 {%0, %1}, %2;" : "=f"(lo), "=f"(hi) : "l"(d))

// ---------------- constant memory: conv weights/bias ----------------
__constant__ __align__(16) float c_w[9 * 4 * CH_];
__constant__ __align__(16) float c_b[CH_];

// ---------------- device scratch (static: no runtime allocation) ----------------
__device__ float2 g_tw[W_];                          // e^{+i 2pi k/224} table
__device__ float2 g_R[(size_t)TB_*H_*WFP_];          // row rFFT results (padded)
__device__ float  g_mag[(size_t)TB_*H_*WF_];         // log1p|spec|
__device__ float  g_epart[TB_*NWG_];                 // energy partial sums
__device__ int    g_count[T_*B_*CH_];                // spike counts per (t,b,ch)

// ---------------- init: twiddles + zero ALL counters every call ----------------
__global__ void init_kernel() {
    int i = blockIdx.x * blockDim.x + threadIdx.x;
    if (i < W_) {
        double a = (2.0 * 3.141592653589793238462643 * (double)i) / 224.0;
        g_tw[i] = make_float2((float)cos(a), (float)sin(a));
    }
    if (i < T_ * B_ * CH_) g_count[i] = 0;
}

// ---------------- row rFFT: real-fold (half steps) + f32x2 packed complex acc ----------------
// grid (TB_*H_/8), block 128. Thread owns wf (0..119), 8 rows.
// X[wf] = g0 + (-1)^wf g112 + sum_{n=1..111} a[n] cos - i b[n] sin;  a=g[n]+g[224-n], b=g[n]-g[224-n]
__global__ void __launch_bounds__(128) rowfft_kernel(const float* __restrict__ x) {
    __shared__ float  gsh[8][W_];
    __shared__ __align__(8) float2 ab[8][112];   // {a,b} folded pairs (n=0: {g0,0})
    __shared__ float2 twsh[W_];
    int tid = threadIdx.x;
    int rid0 = blockIdx.x * 8;

    for (int i = tid; i < W_; i += 128) twsh[i] = g_tw[i];
    const float* xb = x + (size_t)rid0 * W_ * 3;
    for (int i = tid; i < 8 * W_; i += 128) {
        float r = xb[i*3+0], g = xb[i*3+1], b = xb[i*3+2];
        ((float*)gsh)[i] = (r + g + b) * (1.0f / 3.0f);
    }
    __syncthreads();

    for (int i = tid; i < 8 * 112; i += 128) {
        int r = i / 112, n = i % 112;
        float a, bv;
        if (n == 0) { a = gsh[r][0]; bv = 0.f; }
        else { float p = gsh[r][n], q = gsh[r][224 - n]; a = p + q; bv = p - q; }
        ab[r][n] = make_float2(a, bv);
    }
    __syncthreads();

    int wf = tid;
    if (wf >= WFP_) return;

    ull acc[8];
    float sg = (wf & 1) ? -1.0f : 1.0f;
    #pragma unroll
    for (int r = 0; r < 8; ++r) {
        float re0 = sg * gsh[r][112];
        PACK_F32X2(acc[r], re0, 0.0f);
    }

    // recurrence state (c, sn=-s); step angle 2*pi*wf/224
    const float cs = twsh[wf].x, ss = twsh[wf].y;
    for (int nb = 0; nb < 112; nb += 16) {
        int idx = (nb * wf) % 224;                   // exact resync
        float c = twsh[idx].x, sn = -twsh[idx].y;
        #pragma unroll
        for (int k = 0; k < 16; ++k) {
            ull Wp; PACK_F32X2(Wp, c, sn);           // {cos, -sin}
            #pragma unroll
            for (int r = 0; r < 8; ++r) {
                ull abv = *(const ull*)&ab[r][nb + k];   // broadcast LDS.64
                FMA_F32X2(acc[r], abv, Wp);          // re+=a*c, im+=b*(-s)
            }
            float cn = c * cs + sn * ss;
            sn = sn * cs - c * ss;
            c = cn;
        }
    }
    #pragma unroll
    for (int r = 0; r < 8; ++r) {
        float re, im; UNPACK_F32X2(re, im, acc[r]);
        g_R[(size_t)(rid0 + r) * WFP_ + wf] = make_float2(re, im);
    }
}

// ---------------- column FFT: radix-2 DIT + f32x2 packed, 8 wf-columns per block ----------------
// Threads 0..111: E[k] over even rows; 112..223: O[k] over odd rows (identical instr stream).
// Combine: X[k] = E[k] + tw224[k]*O[k]; X[k+112] = E[k] - tw224[k]*O[k].
__global__ void __launch_bounds__(224) colfft_kernel() {
    __shared__ __align__(16) char pool[8 * 224 * 16];   // dup[j][h] then E/O exchange
    __shared__ float2 twsh[H_];
    __shared__ float  red[7];
    int tid = threadIdx.x;
    int wf0 = blockIdx.x * 8;
    int tb  = blockIdx.y;

    twsh[tid] = g_tw[tid];
    {   // stage duplicated: dup[j][h] = {vx,vx},{vy,vy} (16B)
        ulonglong2* dup = (ulonglong2*)pool;
        const float4* src = (const float4*)(g_R + ((size_t)tb * H_ + tid) * WFP_ + wf0);
        #pragma unroll
        for (int q = 0; q < 4; ++q) {
            float4 v = src[q];
            ull d0, d1, d2, d3;
            PACK_F32X2(d0, v.x, v.x); PACK_F32X2(d1, v.y, v.y);
            PACK_F32X2(d2, v.z, v.z); PACK_F32X2(d3, v.w, v.w);
            dup[(2*q+0) * 224 + tid] = make_ulonglong2(d0, d1);
            dup[(2*q+1) * 224 + tid] = make_ulonglong2(d2, d3);
        }
    }
    __syncthreads();

    int ro = (tid >= 112) ? 1 : 0;
    int k  = tid - 112 * ro;           // 0..111
    int k2 = 2 * k;                    // step angle index (<=222)

    ull acc[8];
    #pragma unroll
    for (int j = 0; j < 8; ++j) acc[j] = 0ull;

    {
        const ulonglong2* dup = (const ulonglong2*)pool;
        const float cs = twsh[k2].x, ss = twsh[k2].y;
        for (int mb = 0; mb < 112; mb += 16) {
            int idx = (k2 * mb) % 224;
            float c = twsh[idx].x, sn = -twsh[idx].y;
            #pragma unroll
            for (int mm = 0; mm < 16; ++mm) {
                int h = 2 * (mb + mm) + ro;
                ull W1; PACK_F32X2(W1, c, sn);       // {c,-s}
                float snn = -sn;
                ull W2; PACK_F32X2(W2, snn, c);      // {s, c}
                #pragma unroll
                for (int j = 0; j < 8; ++j) {
                    ulonglong2 d = dup[j * 224 + h]; // broadcast LDS.128
                    FMA_F32X2(acc[j], d.x, W1);      // re+=vx c, im-=vx s
                    FMA_F32X2(acc[j], d.y, W2);      // re+=vy s, im+=vy c
                }
                float cn = c * cs + sn * ss;
                sn = sn * cs - c * ss;
                c = cn;
            }
        }
    }
    __syncthreads();                                  // done reading dup; reuse pool

    ull* Ebuf = (ull*)pool;                           // [8][112]
    ull* Obuf = (ull*)pool + 8 * 112;                 // [8][112]
    {
        ull* my = ro ? Obuf : Ebuf;
        #pragma unroll
        for (int j = 0; j < 8; ++j) my[j * 112 + k] = acc[j];
    }
    __syncthreads();

    // combine + mag + energy; thread tid -> output row hf = tid
    float sg = ro ? -1.0f : 1.0f;
    float ck = twsh[k].x, sk = twsh[k].y;             // e^{-2pi i k/224} = (ck, -sk)
    float a1 = sg * ck, a2 = -sg * sk, a3 = sg * sk;
    ull W1p; PACK_F32X2(W1p, a1, a2);
    ull W2p; PACK_F32X2(W2p, a3, a1);

    float esum = 0.f;
    float* mrow = g_mag + ((size_t)tb * H_ + tid) * WF_;
    #pragma unroll
    for (int j = 0; j < 8; ++j) {
        ull X = Ebuf[j * 112 + k];
        ull O = Obuf[j * 112 + k];
        float orr, oii; UNPACK_F32X2(orr, oii, O);
        ull P1; PACK_F32X2(P1, orr, orr);
        ull P2; PACK_F32X2(P2, oii, oii);
        FMA_F32X2(X, P1, W1p);
        FMA_F32X2(X, P2, W2p);
        float re, im; UNPACK_F32X2(re, im, X);
        int wf = wf0 + j;
        if (wf < WF_) {
            float m = log1pf(sqrtf(re * re + im * im));
            mrow[wf] = m;
            esum += m;
        }
    }
    #pragma unroll
    for (int o = 16; o; o >>= 1) esum += __shfl_down_sync(0xffffffffu, esum, o);
    if ((tid & 31) == 0) red[tid >> 5] = esum;
    __syncthreads();
    if (tid == 0) {
        float tot = 0.f;
        #pragma unroll
        for (int i = 0; i < 7; ++i) tot += red[i];
        g_epart[tb * NWG_ + blockIdx.x] = tot;
    }
}

// ---------------- fused conv3x3(4->32) + LIF, f32x2 channel-pair packed (unchanged) ----------------
#define PLS_ 360   // 18*20 floats per plane

__device__ __forceinline__ void fill_tile(float* __restrict__ pls,
                                          const float* __restrict__ x,
                                          int t, int b, int by0, int bx0, int tid) {
    const float sc = (float)WF_ / (float)W_;
    for (int i = tid; i < 18 * 18; i += 256) {
        int ly = i / 18, lx = i % 18;
        int gy = by0 + ly - 1, gx = bx0 + lx - 1;
        float vr = 0.f, vg = 0.f, vb = 0.f, vm = 0.f;
        if (gy >= 0 && gy < H_ && gx >= 0 && gx < W_) {
            size_t base = (((size_t)t * B_ + b) * H_ + gy) * W_ + gx;
            const float* px = x + base * 3;
            vr = px[0]; vg = px[1]; vb = px[2];
            float u  = (gx + 0.5f) * sc - 0.5f;
            float fj = floorf(u);
            float f  = u - fj;
            int j = (int)fj;
            int i0 = j < 0 ? 0 : (j > WF_-1 ? WF_-1 : j);
            int i1 = j+1 < 0 ? 0 : (j+1 > WF_-1 ? WF_-1 : j+1);
            const float* mrow = g_mag + (((size_t)t * B_ + b) * H_ + gy) * WF_;
            vm = (1.0f - f) * mrow[i0] + f * mrow[i1];
        }
        int o = ly * 20 + lx;
        pls[0*PLS_ + o] = vr;
        pls[1*PLS_ + o] = vg;
        pls[2*PLS_ + o] = vb;
        pls[3*PLS_ + o] = vm;
    }
}

__global__ void __launch_bounds__(256, 2) convlif_kernel(const float* __restrict__ x) {
    __shared__ __align__(16) float planes[2][4 * PLS_];
    __shared__ int cnt[T_][CH_];

    int tid = threadIdx.x;
    int w = tid >> 5;
    int l = tid & 31;
    int r = l >> 1;
    int hx = l & 1;
    int c0 = hx * 8;
    int b = blockIdx.z;
    int by0 = blockIdx.y * 16, bx0 = blockIdx.x * 16;

    for (int i = tid; i < T_ * CH_; i += 256) ((int*)cnt)[i] = 0;

    const ull* cw2 = (const ull*)c_w;
    const ull* cb2 = (const ull*)c_b;

    ull bias2[2];
    bias2[0] = cb2[2*w + 0];
    bias2[1] = cb2[2*w + 1];

    ull K09;
    { float k = 0.9f; PACK_F32X2(K09, k, k); }

    ull V2[2][8];
    #pragma unroll
    for (int c = 0; c < 2; ++c)
        #pragma unroll
        for (int j = 0; j < 8; ++j) V2[c][j] = 0ull;

    fill_tile(&planes[0][0], x, 0, b, by0, bx0, tid);
    __syncthreads();

    #pragma unroll 1
    for (int t = 0; t < T_; ++t) {
        int bb = t & 1;
        if (t + 1 < T_) fill_tile(&planes[bb ^ 1][0], x, t + 1, b, by0, bx0, tid);

        ull acc[2][8];
        #pragma unroll
        for (int c = 0; c < 2; ++c)
            #pragma unroll
            for (int j = 0; j < 8; ++j) acc[c][j] = bias2[c];

        #pragma unroll
        for (int ky = 0; ky < 3; ++ky) {
            #pragma unroll
            for (int ic = 0; ic < 4; ++ic) {
                const float* pl = &planes[bb][ic * PLS_ + (r + ky) * 20 + c0];
                float4 a0 = *(const float4*)(pl + 0);
                float4 a1 = *(const float4*)(pl + 4);
                float2 a2 = *(const float2*)(pl + 8);
                ull A[10];
                PACK_F32X2(A[0], a0.x, a0.x);
                PACK_F32X2(A[1], a0.y, a0.y);
                PACK_F32X2(A[2], a0.z, a0.z);
                PACK_F32X2(A[3], a0.w, a0.w);
                PACK_F32X2(A[4], a1.x, a1.x);
                PACK_F32X2(A[5], a1.y, a1.y);
                PACK_F32X2(A[6], a1.z, a1.z);
                PACK_F32X2(A[7], a1.w, a1.w);
                PACK_F32X2(A[8], a2.x, a2.x);
                PACK_F32X2(A[9], a2.y, a2.y);
                #pragma unroll
                for (int kx = 0; kx < 3; ++kx) {
                    int p = ky * 3 + kx;
                    ull w0 = cw2[(p * 4 + ic) * 16 + 2*w + 0];
                    ull w1 = cw2[(p * 4 + ic) * 16 + 2*w + 1];
                    #pragma unroll
                    for (int j = 0; j < 8; ++j) {
                        FMA_F32X2(acc[0][j], A[j + kx], w0);
                        FMA_F32X2(acc[1][j], A[j + kx], w1);
                    }
                }
            }
        }

        int n[4] = {0, 0, 0, 0};
        #pragma unroll
        for (int c = 0; c < 2; ++c) {
            #pragma unroll
            for (int j = 0; j < 8; ++j) {
                FMA_F32X2(acc[c][j], V2[c][j], K09);
                float lo, hi;
                UNPACK_F32X2(lo, hi, acc[c][j]);
                if (lo > 1.0f) { lo -= 1.0f; n[2*c+0]++; }
                if (hi > 1.0f) { hi -= 1.0f; n[2*c+1]++; }
                PACK_F32X2(V2[c][j], lo, hi);
            }
        }
        int p01 = n[0] | (n[1] << 16);
        int p23 = n[2] | (n[3] << 16);
        #pragma unroll
        for (int o = 16; o; o >>= 1) {
            p01 += __shfl_down_sync(0xffffffffu, p01, o);
            p23 += __shfl_down_sync(0xffffffffu, p23, o);
        }
        if (l == 0) {
            cnt[t][4*w + 0] += p01 & 0xffff;
            cnt[t][4*w + 1] += p01 >> 16;
            cnt[t][4*w + 2] += p23 & 0xffff;
            cnt[t][4*w + 3] += p23 >> 16;
        }
        __syncthreads();
    }

    for (int i = tid; i < T_ * CH_; i += 256) {
        int t = i >> 5, ch = i & 31;
        atomicAdd(&g_count[(t * B_ + b) * CH_ + ch], cnt[t][ch]);
    }
}

// ---------------- finalize: logits, readout, spike rate, energy ----------------
__global__ void __launch_bounds__(256) finalize_kernel(const float* __restrict__ hw_g,
                                                       const float* __restrict__ hb_g,
                                                       float* __restrict__ out, int out_size) {
    __shared__ float hw[CH_ * OUT_];
    __shared__ float hb[OUT_];
    __shared__ float logits[T_ * B_ * OUT_];
    __shared__ float red[256];
    int tid = threadIdx.x;
    for (int i = tid; i < CH_ * OUT_; i += 256) hw[i] = hw_g[i];
    if (tid < OUT_) hb[tid] = hb_g[tid];
    __syncthreads();

    const float inv = 1.0f / ((float)(H_ * W_));
    for (int i = tid; i < T_ * B_ * OUT_; i += 256) {
        int o = i % OUT_;
        int tb = i / OUT_;
        float a = hb[o];
        const int* c = &g_count[tb * CH_];
        #pragma unroll
        for (int ch = 0; ch < CH_; ++ch)
            a += ((float)c[ch] * inv) * hw[ch * OUT_ + o];
        logits[i] = a;
    }
    __syncthreads();

    if (out_size >= B_*OUT_ + T_*B_*OUT_ + 2) {
        for (int i = tid; i < T_ * B_ * OUT_; i += 256)
            out[B_ * OUT_ + i] = logits[i];
    }
    if (tid < B_ * OUT_) {
        float s = 0.f;
        for (int t = 0; t < T_; ++t) s += logits[t * B_ * OUT_ + tid];
        out[tid] = s * (1.0f / (float)T_);
    }

    {   // spike rate
        float s = 0.f;
        for (int i = tid; i < T_ * B_ * CH_; i += 256) s += (float)g_count[i];
        red[tid] = s;
        __syncthreads();
        for (int st = 128; st; st >>= 1) { if (tid < st) red[tid] += red[tid + st]; __syncthreads(); }
        if (tid == 0 && out_size >= B_*OUT_ + T_*B_*OUT_ + 1)
            out[B_*OUT_ + T_*B_*OUT_] = red[0] / ((float)T_ * B_ * CH_ * H_ * W_);
        __syncthreads();
    }
    {   // spectral energy
        float s = 0.f;
        for (int i = tid; i < TB_ * NWG_; i += 256) s += g_epart[i];
        red[tid] = s;
        __syncthreads();
        for (int st = 128; st; st >>= 1) { if (tid < st) red[tid] += red[tid + st]; __syncthreads(); }
        if (tid == 0 && out_size >= B_*OUT_ + T_*B_*OUT_ + 2)
            out[B_*OUT_ + T_*B_*OUT_ + 1] = red[0] / ((float)T_ * B_ * H_ * WF_);
    }
}

// ---------------- launch ----------------
extern "C" void kernel_launch(void* const* d_in, const int* in_sizes, int n_in,
                              void* d_out, int out_size) {
    const float* x_seq  = (const float*)d_in[0];
    const float* conv_w = (const float*)d_in[1];
    const float* conv_b = (const float*)d_in[2];
    const float* head_w = (const float*)d_in[3];
    const float* head_b = (const float*)d_in[4];
    float* out = (float*)d_out;

    cudaMemcpyToSymbolAsync(c_w, conv_w, 9 * 4 * CH_ * sizeof(float), 0, cudaMemcpyDeviceToDevice, 0);
    cudaMemcpyToSymbolAsync(c_b, conv_b, CH_ * sizeof(float), 0, cudaMemcpyDeviceToDevice, 0);

    init_kernel<<<16, 256>>>();
    rowfft_kernel<<<TB_ * H_ / 8, 128>>>(x_seq);
    colfft_kernel<<<dim3(NWG_, TB_), 224>>>();
    convlif_kernel<<<dim3(W_/16, H_/16, B_), 256>>>(x_seq);
    finalize_kernel<<<1, 256>>>(head_w, head_b, out, out_size);
}

// round 8
// speedup vs baseline: 3.1826x; 1.0113x over previous
#include <cuda_runtime.h>
#include <math.h>

#define T_ 16
#define B_ 8
#define H_ 224
#define W_ 224
#define C_ 3
#define CH_ 32
#define OUT_ 10
#define WF_ 113           // W/2 + 1
#define WFP_ 120          // padded to multiple of 8 for vectorized colfft
#define NWG_ 15           // WFP_/8 wf-groups
#define TB_ (T_*B_)

typedef unsigned long long ull;

#define FMA_F32X2(d, a, b) asm("fma.rn.f32x2 %0, %1, %2, %0;" : "+l"(d) : "l"(a), "l"(b))
#define PACK_F32X2(d, lo, hi) asm("mov.b64 %0, {%1, %2};" : "=l"(d) : "f"(lo), "f"(hi))
#define UNPACK_F32X2(lo, hi, d) asm("mov.b64 {%0, %1}, %2;" : "=f"(lo), "=f"(hi) : "l"(d))

// ---------------- device scratch (static: no runtime allocation) ----------------
__device__ float2 g_tw[W_];                          // e^{+i 2pi k/224} table
__device__ float2 g_R[(size_t)TB_*H_*WFP_];          // row rFFT results (padded)
__device__ float  g_mag[(size_t)TB_*H_*WF_];         // log1p|spec|
__device__ float  g_epart[TB_*NWG_];                 // energy partial sums
__device__ int    g_count[T_*B_*CH_];                // spike counts per (t,b,ch)

// ---------------- init: twiddles + zero ALL counters every call ----------------
__global__ void init_kernel() {
    int i = blockIdx.x * blockDim.x + threadIdx.x;
    if (i < W_) {
        double a = (2.0 * 3.141592653589793238462643 * (double)i) / 224.0;
        g_tw[i] = make_float2((float)cos(a), (float)sin(a));
    }
    if (i < T_ * B_ * CH_) g_count[i] = 0;
}

// ---------------- row rFFT: real-fold (half steps) + f32x2 packed complex acc ----------------
__global__ void __launch_bounds__(128) rowfft_kernel(const float* __restrict__ x) {
    __shared__ float  gsh[8][W_];
    __shared__ __align__(8) float2 ab[8][112];
    __shared__ float2 twsh[W_];
    int tid = threadIdx.x;
    int rid0 = blockIdx.x * 8;

    for (int i = tid; i < W_; i += 128) twsh[i] = g_tw[i];
    const float* xb = x + (size_t)rid0 * W_ * 3;
    for (int i = tid; i < 8 * W_; i += 128) {
        float r = xb[i*3+0], g = xb[i*3+1], b = xb[i*3+2];
        ((float*)gsh)[i] = (r + g + b) * (1.0f / 3.0f);
    }
    __syncthreads();

    for (int i = tid; i < 8 * 112; i += 128) {
        int r = i / 112, n = i % 112;
        float a, bv;
        if (n == 0) { a = gsh[r][0]; bv = 0.f; }
        else { float p = gsh[r][n], q = gsh[r][224 - n]; a = p + q; bv = p - q; }
        ab[r][n] = make_float2(a, bv);
    }
    __syncthreads();

    int wf = tid;
    if (wf >= WFP_) return;

    ull acc[8];
    float sg = (wf & 1) ? -1.0f : 1.0f;
    #pragma unroll
    for (int r = 0; r < 8; ++r) {
        float re0 = sg * gsh[r][112];
        PACK_F32X2(acc[r], re0, 0.0f);
    }

    const float cs = twsh[wf].x, ss = twsh[wf].y;
    for (int nb = 0; nb < 112; nb += 16) {
        int idx = (nb * wf) % 224;
        float c = twsh[idx].x, sn = -twsh[idx].y;
        #pragma unroll
        for (int k = 0; k < 16; ++k) {
            ull Wp; PACK_F32X2(Wp, c, sn);
            #pragma unroll
            for (int r = 0; r < 8; ++r) {
                ull abv = *(const ull*)&ab[r][nb + k];
                FMA_F32X2(acc[r], abv, Wp);
            }
            float cn = c * cs + sn * ss;
            sn = sn * cs - c * ss;
            c = cn;
        }
    }
    #pragma unroll
    for (int r = 0; r < 8; ++r) {
        float re, im; UNPACK_F32X2(re, im, acc[r]);
        g_R[(size_t)(rid0 + r) * WFP_ + wf] = make_float2(re, im);
    }
}

// ---------------- column FFT: radix-2 DIT + f32x2 packed, 8 wf-columns per block ----------------
__global__ void __launch_bounds__(224) colfft_kernel() {
    __shared__ __align__(16) char pool[8 * 224 * 16];
    __shared__ float2 twsh[H_];
    __shared__ float  red[7];
    int tid = threadIdx.x;
    int wf0 = blockIdx.x * 8;
    int tb  = blockIdx.y;

    twsh[tid] = g_tw[tid];
    {
        ulonglong2* dup = (ulonglong2*)pool;
        const float4* src = (const float4*)(g_R + ((size_t)tb * H_ + tid) * WFP_ + wf0);
        #pragma unroll
        for (int q = 0; q < 4; ++q) {
            float4 v = src[q];
            ull d0, d1, d2, d3;
            PACK_F32X2(d0, v.x, v.x); PACK_F32X2(d1, v.y, v.y);
            PACK_F32X2(d2, v.z, v.z); PACK_F32X2(d3, v.w, v.w);
            dup[(2*q+0) * 224 + tid] = make_ulonglong2(d0, d1);
            dup[(2*q+1) * 224 + tid] = make_ulonglong2(d2, d3);
        }
    }
    __syncthreads();

    int ro = (tid >= 112) ? 1 : 0;
    int k  = tid - 112 * ro;
    int k2 = 2 * k;

    ull acc[8];
    #pragma unroll
    for (int j = 0; j < 8; ++j) acc[j] = 0ull;

    {
        const ulonglong2* dup = (const ulonglong2*)pool;
        const float cs = twsh[k2].x, ss = twsh[k2].y;
        for (int mb = 0; mb < 112; mb += 16) {
            int idx = (k2 * mb) % 224;
            float c = twsh[idx].x, sn = -twsh[idx].y;
            #pragma unroll
            for (int mm = 0; mm < 16; ++mm) {
                int h = 2 * (mb + mm) + ro;
                ull W1; PACK_F32X2(W1, c, sn);
                float snn = -sn;
                ull W2; PACK_F32X2(W2, snn, c);
                #pragma unroll
                for (int j = 0; j < 8; ++j) {
                    ulonglong2 d = dup[j * 224 + h];
                    FMA_F32X2(acc[j], d.x, W1);
                    FMA_F32X2(acc[j], d.y, W2);
                }
                float cn = c * cs + sn * ss;
                sn = sn * cs - c * ss;
                c = cn;
            }
        }
    }
    __syncthreads();

    ull* Ebuf = (ull*)pool;
    ull* Obuf = (ull*)pool + 8 * 112;
    {
        ull* my = ro ? Obuf : Ebuf;
        #pragma unroll
        for (int j = 0; j < 8; ++j) my[j * 112 + k] = acc[j];
    }
    __syncthreads();

    float sg = ro ? -1.0f : 1.0f;
    float ck = twsh[k].x, sk = twsh[k].y;
    float a1 = sg * ck, a2 = -sg * sk, a3 = sg * sk;
    ull W1p; PACK_F32X2(W1p, a1, a2);
    ull W2p; PACK_F32X2(W2p, a3, a1);

    float esum = 0.f;
    float* mrow = g_mag + ((size_t)tb * H_ + tid) * WF_;
    #pragma unroll
    for (int j = 0; j < 8; ++j) {
        ull X = Ebuf[j * 112 + k];
        ull O = Obuf[j * 112 + k];
        float orr, oii; UNPACK_F32X2(orr, oii, O);
        ull P1; PACK_F32X2(P1, orr, orr);
        ull P2; PACK_F32X2(P2, oii, oii);
        FMA_F32X2(X, P1, W1p);
        FMA_F32X2(X, P2, W2p);
        float re, im; UNPACK_F32X2(re, im, X);
        int wf = wf0 + j;
        if (wf < WF_) {
            float m = log1pf(sqrtf(re * re + im * im));
            mrow[wf] = m;
            esum += m;
        }
    }
    #pragma unroll
    for (int o = 16; o; o >>= 1) esum += __shfl_down_sync(0xffffffffu, esum, o);
    if ((tid & 31) == 0) red[tid >> 5] = esum;
    __syncthreads();
    if (tid == 0) {
        float tot = 0.f;
        #pragma unroll
        for (int i = 0; i < 7; ++i) tot += red[i];
        g_epart[tb * NWG_ + blockIdx.x] = tot;
    }
}

// ---------------- fused conv3x3(4->32) + LIF: weights as smem broadcast LDS.128 quads --------
// Per (p,ic,warpgroup) one ulonglong2 {chpair01, chpair23}; warp-uniform address ->
// broadcast LDS.128 (1 wavefront) instead of 2x LDC.64 (half-rate constant port, floor 8).
#define PLS_ 360   // 18*20 floats per plane

__device__ __forceinline__ void fill_tile(float* __restrict__ pls,
                                          const float* __restrict__ x,
                                          int t, int b, int by0, int bx0, int tid) {
    const float sc = (float)WF_ / (float)W_;
    for (int i = tid; i < 18 * 18; i += 256) {
        int ly = i / 18, lx = i % 18;
        int gy = by0 + ly - 1, gx = bx0 + lx - 1;
        float vr = 0.f, vg = 0.f, vb = 0.f, vm = 0.f;
        if (gy >= 0 && gy < H_ && gx >= 0 && gx < W_) {
            size_t base = (((size_t)t * B_ + b) * H_ + gy) * W_ + gx;
            const float* px = x + base * 3;
            vr = px[0]; vg = px[1]; vb = px[2];
            float u  = (gx + 0.5f) * sc - 0.5f;
            float fj = floorf(u);
            float f  = u - fj;
            int j = (int)fj;
            int i0 = j < 0 ? 0 : (j > WF_-1 ? WF_-1 : j);
            int i1 = j+1 < 0 ? 0 : (j+1 > WF_-1 ? WF_-1 : j+1);
            const float* mrow = g_mag + (((size_t)t * B_ + b) * H_ + gy) * WF_;
            vm = (1.0f - f) * mrow[i0] + f * mrow[i1];
        }
        int o = ly * 20 + lx;
        pls[0*PLS_ + o] = vr;
        pls[1*PLS_ + o] = vg;
        pls[2*PLS_ + o] = vb;
        pls[3*PLS_ + o] = vm;
    }
}

__global__ void __launch_bounds__(256, 2) convlif_kernel(const float* __restrict__ x,
                                                         const float* __restrict__ cw,
                                                         const float* __restrict__ cb) {
    __shared__ __align__(16) float planes[2][4 * PLS_];
    __shared__ __align__(16) ulonglong2 wq[9][4][8];   // [p][ic][warpgroup] = {pair01, pair23}
    __shared__ float bsh[CH_];
    __shared__ int cnt[T_][CH_];

    int tid = threadIdx.x;
    int w = tid >> 5;
    int l = tid & 31;
    int r = l >> 1;
    int hx = l & 1;
    int c0 = hx * 8;
    int b = blockIdx.z;
    int by0 = blockIdx.y * 16, bx0 = blockIdx.x * 16;

    for (int i = tid; i < T_ * CH_; i += 256) ((int*)cnt)[i] = 0;
    // stage weight quads: entry i = (p*4+ic)*8 + wg  -> 4 consecutive floats cw[(p*4+ic)*32 + 4*wg]
    for (int i = tid; i < 9 * 4 * 8; i += 256) {
        int pi = i >> 3, wg = i & 7;
        const float* src = cw + pi * CH_ + 4 * wg;
        ull q0, q1;
        PACK_F32X2(q0, src[0], src[1]);
        PACK_F32X2(q1, src[2], src[3]);
        ((ulonglong2*)wq)[i] = make_ulonglong2(q0, q1);
    }
    if (tid < CH_) bsh[tid] = cb[tid];

    fill_tile(&planes[0][0], x, 0, b, by0, bx0, tid);
    __syncthreads();

    ull bias2[2];
    { float b0 = bsh[4*w+0], b1 = bsh[4*w+1], b2 = bsh[4*w+2], b3 = bsh[4*w+3];
      PACK_F32X2(bias2[0], b0, b1);
      PACK_F32X2(bias2[1], b2, b3); }

    ull K09;
    { float k = 0.9f; PACK_F32X2(K09, k, k); }

    ull V2[2][8];
    #pragma unroll
    for (int c = 0; c < 2; ++c)
        #pragma unroll
        for (int j = 0; j < 8; ++j) V2[c][j] = 0ull;

    #pragma unroll 1
    for (int t = 0; t < T_; ++t) {
        int bb = t & 1;
        if (t + 1 < T_) fill_tile(&planes[bb ^ 1][0], x, t + 1, b, by0, bx0, tid);

        ull acc[2][8];
        #pragma unroll
        for (int c = 0; c < 2; ++c)
            #pragma unroll
            for (int j = 0; j < 8; ++j) acc[c][j] = bias2[c];

        #pragma unroll
        for (int ky = 0; ky < 3; ++ky) {
            #pragma unroll
            for (int ic = 0; ic < 4; ++ic) {
                const float* pl = &planes[bb][ic * PLS_ + (r + ky) * 20 + c0];
                float4 a0 = *(const float4*)(pl + 0);
                float4 a1 = *(const float4*)(pl + 4);
                float2 a2 = *(const float2*)(pl + 8);
                ull A[10];
                PACK_F32X2(A[0], a0.x, a0.x);
                PACK_F32X2(A[1], a0.y, a0.y);
                PACK_F32X2(A[2], a0.z, a0.z);
                PACK_F32X2(A[3], a0.w, a0.w);
                PACK_F32X2(A[4], a1.x, a1.x);
                PACK_F32X2(A[5], a1.y, a1.y);
                PACK_F32X2(A[6], a1.z, a1.z);
                PACK_F32X2(A[7], a1.w, a1.w);
                PACK_F32X2(A[8], a2.x, a2.x);
                PACK_F32X2(A[9], a2.y, a2.y);
                #pragma unroll
                for (int kx = 0; kx < 3; ++kx) {
                    int p = ky * 3 + kx;
                    ulonglong2 q = wq[p][ic][w];   // broadcast LDS.128 (1 wavefront)
                    #pragma unroll
                    for (int j = 0; j < 8; ++j) {
                        FMA_F32X2(acc[0][j], A[j + kx], q.x);
                        FMA_F32X2(acc[1][j], A[j + kx], q.y);
                    }
                }
            }
        }

        int n[4] = {0, 0, 0, 0};
        #pragma unroll
        for (int c = 0; c < 2; ++c) {
            #pragma unroll
            for (int j = 0; j < 8; ++j) {
                FMA_F32X2(acc[c][j], V2[c][j], K09);
                float lo, hi;
                UNPACK_F32X2(lo, hi, acc[c][j]);
                if (lo > 1.0f) { lo -= 1.0f; n[2*c+0]++; }
                if (hi > 1.0f) { hi -= 1.0f; n[2*c+1]++; }
                PACK_F32X2(V2[c][j], lo, hi);
            }
        }
        int p01 = n[0] | (n[1] << 16);
        int p23 = n[2] | (n[3] << 16);
        #pragma unroll
        for (int o = 16; o; o >>= 1) {
            p01 += __shfl_down_sync(0xffffffffu, p01, o);
            p23 += __shfl_down_sync(0xffffffffu, p23, o);
        }
        if (l == 0) {
            cnt[t][4*w + 0] += p01 & 0xffff;
            cnt[t][4*w + 1] += p01 >> 16;
            cnt[t][4*w + 2] += p23 & 0xffff;
            cnt[t][4*w + 3] += p23 >> 16;
        }
        __syncthreads();
    }

    for (int i = tid; i < T_ * CH_; i += 256) {
        int t = i >> 5, ch = i & 31;
        atomicAdd(&g_count[(t * B_ + b) * CH_ + ch], cnt[t][ch]);
    }
}

// ---------------- finalize: logits, readout, spike rate, energy ----------------
__global__ void __launch_bounds__(256) finalize_kernel(const float* __restrict__ hw_g,
                                                       const float* __restrict__ hb_g,
                                                       float* __restrict__ out, int out_size) {
    __shared__ float hw[CH_ * OUT_];
    __shared__ float hb[OUT_];
    __shared__ float logits[T_ * B_ * OUT_];
    __shared__ float red[256];
    int tid = threadIdx.x;
    for (int i = tid; i < CH_ * OUT_; i += 256) hw[i] = hw_g[i];
    if (tid < OUT_) hb[tid] = hb_g[tid];
    __syncthreads();

    const float inv = 1.0f / ((float)(H_ * W_));
    for (int i = tid; i < T_ * B_ * OUT_; i += 256) {
        int o = i % OUT_;
        int tb = i / OUT_;
        float a = hb[o];
        const int* c = &g_count[tb * CH_];
        #pragma unroll
        for (int ch = 0; ch < CH_; ++ch)
            a += ((float)c[ch] * inv) * hw[ch * OUT_ + o];
        logits[i] = a;
    }
    __syncthreads();

    if (out_size >= B_*OUT_ + T_*B_*OUT_ + 2) {
        for (int i = tid; i < T_ * B_ * OUT_; i += 256)
            out[B_ * OUT_ + i] = logits[i];
    }
    if (tid < B_ * OUT_) {
        float s = 0.f;
        for (int t = 0; t < T_; ++t) s += logits[t * B_ * OUT_ + tid];
        out[tid] = s * (1.0f / (float)T_);
    }

    {   // spike rate
        float s = 0.f;
        for (int i = tid; i < T_ * B_ * CH_; i += 256) s += (float)g_count[i];
        red[tid] = s;
        __syncthreads();
        for (int st = 128; st; st >>= 1) { if (tid < st) red[tid] += red[tid + st]; __syncthreads(); }
        if (tid == 0 && out_size >= B_*OUT_ + T_*B_*OUT_ + 1)
            out[B_*OUT_ + T_*B_*OUT_] = red[0] / ((float)T_ * B_ * CH_ * H_ * W_);
        __syncthreads();
    }
    {   // spectral energy
        float s = 0.f;
        for (int i = tid; i < TB_ * NWG_; i += 256) s += g_epart[i];
        red[tid] = s;
        __syncthreads();
        for (int st = 128; st; st >>= 1) { if (tid < st) red[tid] += red[tid + st]; __syncthreads(); }
        if (tid == 0 && out_size >= B_*OUT_ + T_*B_*OUT_ + 2)
            out[B_*OUT_ + T_*B_*OUT_ + 1] = red[0] / ((float)T_ * B_ * H_ * WF_);
    }
}

// ---------------- launch ----------------
extern "C" void kernel_launch(void* const* d_in, const int* in_sizes, int n_in,
                              void* d_out, int out_size) {
    const float* x_seq  = (const float*)d_in[0];
    const float* conv_w = (const float*)d_in[1];
    const float* conv_b = (const float*)d_in[2];
    const float* head_w = (const float*)d_in[3];
    const float* head_b = (const float*)d_in[4];
    float* out = (float*)d_out;

    init_kernel<<<16, 256>>>();
    rowfft_kernel<<<TB_ * H_ / 8, 128>>>(x_seq);
    colfft_kernel<<<dim3(NWG_, TB_), 224>>>();
    convlif_kernel<<<dim3(W_/16, H_/16, B_), 256>>>(x_seq, conv_w, conv_b);
    finalize_kernel<<<1, 256>>>(head_w, head_b, out, out_size);
}

// round 9
// speedup vs baseline: 3.2569x; 1.0233x over previous
#include <cuda_runtime.h>
#include <math.h>

#define T_ 16
#define B_ 8
#define H_ 224
#define W_ 224
#define C_ 3
#define CH_ 32
#define OUT_ 10
#define WF_ 113           // W/2 + 1
#define WFP_ 120          // padded to multiple of 8 for vectorized colfft
#define NWG_ 15           // WFP_/8 wf-groups
#define TB_ (T_*B_)

typedef unsigned long long ull;

#define FMA_F32X2(d, a, b) asm("fma.rn.f32x2 %0, %1, %2, %0;" : "+l"(d) : "l"(a), "l"(b))
#define PACK_F32X2(d, lo, hi) asm("mov.b64 %0, {%1, %2};" : "=l"(d) : "f"(lo), "f"(hi))
#define UNPACK_F32X2(lo, hi, d) asm("mov.b64 {%0, %1}, %2;" : "=f"(lo), "=f"(hi) : "l"(d))

// ---------------- device scratch (static: no runtime allocation) ----------------
__device__ float2 g_tw[W_];                          // e^{+i 2pi k/224} table
__device__ float2 g_R[(size_t)TB_*H_*WFP_];          // row rFFT results (padded)
__device__ float  g_mag[(size_t)TB_*H_*WF_];         // log1p|spec|
__device__ float  g_epart[TB_*NWG_];                 // energy partial sums
__device__ int    g_count[T_*B_*CH_];                // spike counts per (t,b,ch)

// ---------------- init: twiddles + zero ALL counters every call ----------------
__global__ void init_kernel() {
    int i = blockIdx.x * blockDim.x + threadIdx.x;
    if (i < W_) {
        double a = (2.0 * 3.141592653589793238462643 * (double)i) / 224.0;
        g_tw[i] = make_float2((float)cos(a), (float)sin(a));
    }
    if (i < T_ * B_ * CH_) g_count[i] = 0;
}

// ---------------- row rFFT: real-fold (half steps) + f32x2 packed complex acc ----------------
__global__ void __launch_bounds__(128) rowfft_kernel(const float* __restrict__ x) {
    __shared__ float  gsh[8][W_];
    __shared__ __align__(8) float2 ab[8][112];
    __shared__ float2 twsh[W_];
    int tid = threadIdx.x;
    int rid0 = blockIdx.x * 8;

    for (int i = tid; i < W_; i += 128) twsh[i] = g_tw[i];
    const float* xb = x + (size_t)rid0 * W_ * 3;
    for (int i = tid; i < 8 * W_; i += 128) {
        float r = xb[i*3+0], g = xb[i*3+1], b = xb[i*3+2];
        ((float*)gsh)[i] = (r + g + b) * (1.0f / 3.0f);
    }
    __syncthreads();

    for (int i = tid; i < 8 * 112; i += 128) {
        int r = i / 112, n = i % 112;
        float a, bv;
        if (n == 0) { a = gsh[r][0]; bv = 0.f; }
        else { float p = gsh[r][n], q = gsh[r][224 - n]; a = p + q; bv = p - q; }
        ab[r][n] = make_float2(a, bv);
    }
    __syncthreads();

    int wf = tid;
    if (wf >= WFP_) return;

    ull acc[8];
    float sg = (wf & 1) ? -1.0f : 1.0f;
    #pragma unroll
    for (int r = 0; r < 8; ++r) {
        float re0 = sg * gsh[r][112];
        PACK_F32X2(acc[r], re0, 0.0f);
    }

    const float cs = twsh[wf].x, ss = twsh[wf].y;
    for (int nb = 0; nb < 112; nb += 16) {
        int idx = (nb * wf) % 224;
        float c = twsh[idx].x, sn = -twsh[idx].y;
        #pragma unroll
        for (int k = 0; k < 16; ++k) {
            ull Wp; PACK_F32X2(Wp, c, sn);
            #pragma unroll
            for (int r = 0; r < 8; ++r) {
                ull abv = *(const ull*)&ab[r][nb + k];
                FMA_F32X2(acc[r], abv, Wp);
            }
            float cn = c * cs + sn * ss;
            sn = sn * cs - c * ss;
            c = cn;
        }
    }
    #pragma unroll
    for (int r = 0; r < 8; ++r) {
        float re, im; UNPACK_F32X2(re, im, acc[r]);
        g_R[(size_t)(rid0 + r) * WFP_ + wf] = make_float2(re, im);
    }
}

// ---------------- column FFT: radix-2 DIT + f32x2 packed, 8 wf-columns per block ----------------
__global__ void __launch_bounds__(224) colfft_kernel() {
    __shared__ __align__(16) char pool[8 * 224 * 16];
    __shared__ float2 twsh[H_];
    __shared__ float  red[7];
    int tid = threadIdx.x;
    int wf0 = blockIdx.x * 8;
    int tb  = blockIdx.y;

    twsh[tid] = g_tw[tid];
    {
        ulonglong2* dup = (ulonglong2*)pool;
        const float4* src = (const float4*)(g_R + ((size_t)tb * H_ + tid) * WFP_ + wf0);
        #pragma unroll
        for (int q = 0; q < 4; ++q) {
            float4 v = src[q];
            ull d0, d1, d2, d3;
            PACK_F32X2(d0, v.x, v.x); PACK_F32X2(d1, v.y, v.y);
            PACK_F32X2(d2, v.z, v.z); PACK_F32X2(d3, v.w, v.w);
            dup[(2*q+0) * 224 + tid] = make_ulonglong2(d0, d1);
            dup[(2*q+1) * 224 + tid] = make_ulonglong2(d2, d3);
        }
    }
    __syncthreads();

    int ro = (tid >= 112) ? 1 : 0;
    int k  = tid - 112 * ro;
    int k2 = 2 * k;

    ull acc[8];
    #pragma unroll
    for (int j = 0; j < 8; ++j) acc[j] = 0ull;

    {
        const ulonglong2* dup = (const ulonglong2*)pool;
        const float cs = twsh[k2].x, ss = twsh[k2].y;
        for (int mb = 0; mb < 112; mb += 16) {
            int idx = (k2 * mb) % 224;
            float c = twsh[idx].x, sn = -twsh[idx].y;
            #pragma unroll
            for (int mm = 0; mm < 16; ++mm) {
                int h = 2 * (mb + mm) + ro;
                ull W1; PACK_F32X2(W1, c, sn);
                float snn = -sn;
                ull W2; PACK_F32X2(W2, snn, c);
                #pragma unroll
                for (int j = 0; j < 8; ++j) {
                    ulonglong2 d = dup[j * 224 + h];
                    FMA_F32X2(acc[j], d.x, W1);
                    FMA_F32X2(acc[j], d.y, W2);
                }
                float cn = c * cs + sn * ss;
                sn = sn * cs - c * ss;
                c = cn;
            }
        }
    }
    __syncthreads();

    ull* Ebuf = (ull*)pool;
    ull* Obuf = (ull*)pool + 8 * 112;
    {
        ull* my = ro ? Obuf : Ebuf;
        #pragma unroll
        for (int j = 0; j < 8; ++j) my[j * 112 + k] = acc[j];
    }
    __syncthreads();

    float sg = ro ? -1.0f : 1.0f;
    float ck = twsh[k].x, sk = twsh[k].y;
    float a1 = sg * ck, a2 = -sg * sk, a3 = sg * sk;
    ull W1p; PACK_F32X2(W1p, a1, a2);
    ull W2p; PACK_F32X2(W2p, a3, a1);

    float esum = 0.f;
    float* mrow = g_mag + ((size_t)tb * H_ + tid) * WF_;
    #pragma unroll
    for (int j = 0; j < 8; ++j) {
        ull X = Ebuf[j * 112 + k];
        ull O = Obuf[j * 112 + k];
        float orr, oii; UNPACK_F32X2(orr, oii, O);
        ull P1; PACK_F32X2(P1, orr, orr);
        ull P2; PACK_F32X2(P2, oii, oii);
        FMA_F32X2(X, P1, W1p);
        FMA_F32X2(X, P2, W2p);
        float re, im; UNPACK_F32X2(re, im, X);
        int wf = wf0 + j;
        if (wf < WF_) {
            float m = log1pf(sqrtf(re * re + im * im));
            mrow[wf] = m;
            esum += m;
        }
    }
    #pragma unroll
    for (int o = 16; o; o >>= 1) esum += __shfl_down_sync(0xffffffffu, esum, o);
    if ((tid & 31) == 0) red[tid >> 5] = esum;
    __syncthreads();
    if (tid == 0) {
        float tot = 0.f;
        #pragma unroll
        for (int i = 0; i < 7; ++i) tot += red[i];
        g_epart[tb * NWG_ + blockIdx.x] = tot;
    }
}

// ---------------- fused conv3x3(4->32) + LIF: conflict-free lane->pixel map ----------------
// Lane l -> (row = l&15, half = l>>4): each quarter-warp = 8 CONSECUTIVE rows, same half.
// Plane stride 20 floats -> 4-float-group stride 5 (odd) -> 8 consecutive rows tile all
// 32 banks exactly once -> LDS.128 activation loads are conflict-free (4 wavefronts, was 8).
#define PLS_ 360   // 18*20 floats per plane

__device__ __forceinline__ void fill_tile(float* __restrict__ pls,
                                          const float* __restrict__ x,
                                          int t, int b, int by0, int bx0, int tid) {
    const float sc = (float)WF_ / (float)W_;
    for (int i = tid; i < 18 * 18; i += 256) {
        int ly = i / 18, lx = i % 18;
        int gy = by0 + ly - 1, gx = bx0 + lx - 1;
        float vr = 0.f, vg = 0.f, vb = 0.f, vm = 0.f;
        if (gy >= 0 && gy < H_ && gx >= 0 && gx < W_) {
            size_t base = (((size_t)t * B_ + b) * H_ + gy) * W_ + gx;
            const float* px = x + base * 3;
            vr = px[0]; vg = px[1]; vb = px[2];
            float u  = (gx + 0.5f) * sc - 0.5f;
            float fj = floorf(u);
            float f  = u - fj;
            int j = (int)fj;
            int i0 = j < 0 ? 0 : (j > WF_-1 ? WF_-1 : j);
            int i1 = j+1 < 0 ? 0 : (j+1 > WF_-1 ? WF_-1 : j+1);
            const float* mrow = g_mag + (((size_t)t * B_ + b) * H_ + gy) * WF_;
            vm = (1.0f - f) * mrow[i0] + f * mrow[i1];
        }
        int o = ly * 20 + lx;
        pls[0*PLS_ + o] = vr;
        pls[1*PLS_ + o] = vg;
        pls[2*PLS_ + o] = vb;
        pls[3*PLS_ + o] = vm;
    }
}

__global__ void __launch_bounds__(256, 2) convlif_kernel(const float* __restrict__ x,
                                                         const float* __restrict__ cw,
                                                         const float* __restrict__ cb) {
    __shared__ __align__(16) float planes[2][4 * PLS_];
    __shared__ __align__(16) ulonglong2 wq[9][4][8];   // [p][ic][warpgroup] = {pair01, pair23}
    __shared__ float bsh[CH_];
    __shared__ int cnt[T_][CH_];

    int tid = threadIdx.x;
    int w = tid >> 5;
    int l = tid & 31;
    int r = l & 15;            // CONFLICT-FREE MAP: row = l&15 (was l>>1)
    int hx = l >> 4;           //                    half = l>>4 (was l&1)
    int c0 = hx * 8;
    int b = blockIdx.z;
    int by0 = blockIdx.y * 16, bx0 = blockIdx.x * 16;

    for (int i = tid; i < T_ * CH_; i += 256) ((int*)cnt)[i] = 0;
    for (int i = tid; i < 9 * 4 * 8; i += 256) {
        int pi = i >> 3, wg = i & 7;
        const float* src = cw + pi * CH_ + 4 * wg;
        ull q0, q1;
        PACK_F32X2(q0, src[0], src[1]);
        PACK_F32X2(q1, src[2], src[3]);
        ((ulonglong2*)wq)[i] = make_ulonglong2(q0, q1);
    }
    if (tid < CH_) bsh[tid] = cb[tid];

    fill_tile(&planes[0][0], x, 0, b, by0, bx0, tid);
    __syncthreads();

    ull bias2[2];
    { float b0 = bsh[4*w+0], b1 = bsh[4*w+1], b2 = bsh[4*w+2], b3 = bsh[4*w+3];
      PACK_F32X2(bias2[0], b0, b1);
      PACK_F32X2(bias2[1], b2, b3); }

    ull K09;
    { float k = 0.9f; PACK_F32X2(K09, k, k); }

    ull V2[2][8];
    #pragma unroll
    for (int c = 0; c < 2; ++c)
        #pragma unroll
        for (int j = 0; j < 8; ++j) V2[c][j] = 0ull;

    #pragma unroll 1
    for (int t = 0; t < T_; ++t) {
        int bb = t & 1;
        if (t + 1 < T_) fill_tile(&planes[bb ^ 1][0], x, t + 1, b, by0, bx0, tid);

        ull acc[2][8];
        #pragma unroll
        for (int c = 0; c < 2; ++c)
            #pragma unroll
            for (int j = 0; j < 8; ++j) acc[c][j] = bias2[c];

        #pragma unroll
        for (int ky = 0; ky < 3; ++ky) {
            #pragma unroll
            for (int ic = 0; ic < 4; ++ic) {
                const float* pl = &planes[bb][ic * PLS_ + (r + ky) * 20 + c0];
                float4 a0 = *(const float4*)(pl + 0);
                float4 a1 = *(const float4*)(pl + 4);
                float2 a2 = *(const float2*)(pl + 8);
                ull A[10];
                PACK_F32X2(A[0], a0.x, a0.x);
                PACK_F32X2(A[1], a0.y, a0.y);
                PACK_F32X2(A[2], a0.z, a0.z);
                PACK_F32X2(A[3], a0.w, a0.w);
                PACK_F32X2(A[4], a1.x, a1.x);
                PACK_F32X2(A[5], a1.y, a1.y);
                PACK_F32X2(A[6], a1.z, a1.z);
                PACK_F32X2(A[7], a1.w, a1.w);
                PACK_F32X2(A[8], a2.x, a2.x);
                PACK_F32X2(A[9], a2.y, a2.y);
                #pragma unroll
                for (int kx = 0; kx < 3; ++kx) {
                    int p = ky * 3 + kx;
                    ulonglong2 q = wq[p][ic][w];   // broadcast LDS.128 (1 wavefront)
                    #pragma unroll
                    for (int j = 0; j < 8; ++j) {
                        FMA_F32X2(acc[0][j], A[j + kx], q.x);
                        FMA_F32X2(acc[1][j], A[j + kx], q.y);
                    }
                }
            }
        }

        int n[4] = {0, 0, 0, 0};
        #pragma unroll
        for (int c = 0; c < 2; ++c) {
            #pragma unroll
            for (int j = 0; j < 8; ++j) {
                FMA_F32X2(acc[c][j], V2[c][j], K09);
                float lo, hi;
                UNPACK_F32X2(lo, hi, acc[c][j]);
                if (lo > 1.0f) { lo -= 1.0f; n[2*c+0]++; }
                if (hi > 1.0f) { hi -= 1.0f; n[2*c+1]++; }
                PACK_F32X2(V2[c][j], lo, hi);
            }
        }
        int p01 = n[0] | (n[1] << 16);
        int p23 = n[2] | (n[3] << 16);
        #pragma unroll
        for (int o = 16; o; o >>= 1) {
            p01 += __shfl_down_sync(0xffffffffu, p01, o);
            p23 += __shfl_down_sync(0xffffffffu, p23, o);
        }
        if (l == 0) {
            cnt[t][4*w + 0] += p01 & 0xffff;
            cnt[t][4*w + 1] += p01 >> 16;
            cnt[t][4*w + 2] += p23 & 0xffff;
            cnt[t][4*w + 3] += p23 >> 16;
        }
        __syncthreads();
    }

    for (int i = tid; i < T_ * CH_; i += 256) {
        int t = i >> 5, ch = i & 31;
        atomicAdd(&g_count[(t * B_ + b) * CH_ + ch], cnt[t][ch]);
    }
}

// ---------------- finalize: logits, readout, spike rate, energy ----------------
__global__ void __launch_bounds__(256) finalize_kernel(const float* __restrict__ hw_g,
                                                       const float* __restrict__ hb_g,
                                                       float* __restrict__ out, int out_size) {
    __shared__ float hw[CH_ * OUT_];
    __shared__ float hb[OUT_];
    __shared__ float logits[T_ * B_ * OUT_];
    __shared__ float red[256];
    int tid = threadIdx.x;
    for (int i = tid; i < CH_ * OUT_; i += 256) hw[i] = hw_g[i];
    if (tid < OUT_) hb[tid] = hb_g[tid];
    __syncthreads();

    const float inv = 1.0f / ((float)(H_ * W_));
    for (int i = tid; i < T_ * B_ * OUT_; i += 256) {
        int o = i % OUT_;
        int tb = i / OUT_;
        float a = hb[o];
        const int* c = &g_count[tb * CH_];
        #pragma unroll
        for (int ch = 0; ch < CH_; ++ch)
            a += ((float)c[ch] * inv) * hw[ch * OUT_ + o];
        logits[i] = a;
    }
    __syncthreads();

    if (out_size >= B_*OUT_ + T_*B_*OUT_ + 2) {
        for (int i = tid; i < T_ * B_ * OUT_; i += 256)
            out[B_ * OUT_ + i] = logits[i];
    }
    if (tid < B_ * OUT_) {
        float s = 0.f;
        for (int t = 0; t < T_; ++t) s += logits[t * B_ * OUT_ + tid];
        out[tid] = s * (1.0f / (float)T_);
    }

    {   // spike rate
        float s = 0.f;
        for (int i = tid; i < T_ * B_ * CH_; i += 256) s += (float)g_count[i];
        red[tid] = s;
        __syncthreads();
        for (int st = 128; st; st >>= 1) { if (tid < st) red[tid] += red[tid + st]; __syncthreads(); }
        if (tid == 0 && out_size >= B_*OUT_ + T_*B_*OUT_ + 1)
            out[B_*OUT_ + T_*B_*OUT_] = red[0] / ((float)T_ * B_ * CH_ * H_ * W_);
        __syncthreads();
    }
    {   // spectral energy
        float s = 0.f;
        for (int i = tid; i < TB_ * NWG_; i += 256) s += g_epart[i];
        red[tid] = s;
        __syncthreads();
        for (int st = 128; st; st >>= 1) { if (tid < st) red[tid] += red[tid + st]; __syncthreads(); }
        if (tid == 0 && out_size >= B_*OUT_ + T_*B_*OUT_ + 2)
            out[B_*OUT_ + T_*B_*OUT_ + 1] = red[0] / ((float)T_ * B_ * H_ * WF_);
    }
}

// ---------------- launch ----------------
extern "C" void kernel_launch(void* const* d_in, const int* in_sizes, int n_in,
                              void* d_out, int out_size) {
    const float* x_seq  = (const float*)d_in[0];
    const float* conv_w = (const float*)d_in[1];
    const float* conv_b = (const float*)d_in[2];
    const float* head_w = (const float*)d_in[3];
    const float* head_b = (const float*)d_in[4];
    float* out = (float*)d_out;

    init_kernel<<<16, 256>>>();
    rowfft_kernel<<<TB_ * H_ / 8, 128>>>(x_seq);
    colfft_kernel<<<dim3(NWG_, TB_), 224>>>();
    convlif_kernel<<<dim3(W_/16, H_/16, B_), 256>>>(x_seq, conv_w, conv_b);
    finalize_kernel<<<1, 256>>>(head_w, head_b, out, out_size);
}